// round 13
// baseline (speedup 1.0000x reference)
#include <cuda_runtime.h>
#include <cuda_bf16.h>
#include <cuda_fp16.h>
#include <math.h>
#include <stdint.h>

#define B_   2
#define L_   2048
#define DM   1024
#define DIP  4384
#define DSSM 2048
#define CD   2304
#define NZX  (DSSM + CD)               /* 4352 = z | xBC, dt handled separately */
#define NH   32
#define HD   64
#define DS   128
#define CH   256
#define NC   8

// ---------------- scratch (device globals; no allocation) ----------------
__device__ float g_zx[B_ * L_ * NZX];          // in-proj output (z | xBC)
__device__ float g_xBC[B_ * L_ * CD];          // post-conv+silu (x | B | C)
__device__ float g_dt[B_ * L_ * NH];           // softplus dt (computed in fp32)
__device__ float g_G[B_ * NC * CH * CH];       // per-chunk C@B^T (head-independent)
__device__ float g_cumA[B_ * NC * NH * CH];    // inclusive cumsum of dt*A per chunk
__device__ float g_states[B_ * NC * NH * HD * DS];
__device__ float g_prev[B_ * NC * NH * HD * DS];
__device__ float g_Y[B_ * L_ * DSSM];

// fp16 operand buffers for the two projection GEMMs
__device__ __half g_uh[B_ * L_ * DM];
__device__ __half g_wih[DIP * DM];             // W_in single fp16
__device__ __half g_woh[DM * DSSM];            // W_out single fp16
__device__ __half g_ynh[B_ * L_ * DSSM];

// ---------------- warp-level MMA helpers (arch-neutral PTX) ----------------
__device__ __forceinline__ uint32_t smem_u32(const void* p) {
    uint32_t a;
    asm("{ .reg .u64 t; cvta.to.shared.u64 t, %1; cvt.u32.u64 %0, t; }" : "=r"(a) : "l"(p));
    return a;
}
__device__ __forceinline__ void ldm4(uint32_t* r, uint32_t addr) {
    asm volatile("ldmatrix.sync.aligned.m8n8.x4.shared.b16 {%0,%1,%2,%3}, [%4];"
                 : "=r"(r[0]), "=r"(r[1]), "=r"(r[2]), "=r"(r[3]) : "r"(addr));
}
__device__ __forceinline__ void mma16816h(float* d, const uint32_t* a,
                                          uint32_t b0, uint32_t b1) {
    asm volatile(
        "mma.sync.aligned.m16n8k16.row.col.f32.f16.f16.f32 "
        "{%0,%1,%2,%3}, {%4,%5,%6,%7}, {%8,%9}, {%0,%1,%2,%3};"
        : "+f"(d[0]), "+f"(d[1]), "+f"(d[2]), "+f"(d[3])
        : "r"(a[0]), "r"(a[1]), "r"(a[2]), "r"(a[3]), "r"(b0), "r"(b1));
}
__device__ __forceinline__ void cpasync16(uint32_t dst, const void* src, int sz) {
    asm volatile("cp.async.cg.shared.global [%0], [%1], 16, %2;"
                 :: "r"(dst), "l"(src), "r"(sz) : "memory");
}
#define CP_COMMIT() asm volatile("cp.async.commit_group;" ::: "memory")
#define CP_WAIT0()  asm volatile("cp.async.wait_group 0;" ::: "memory")
#define CP_WAIT1()  asm volatile("cp.async.wait_group 1;" ::: "memory")

// chunk swizzle for 64-byte rows: conflict-free 8-row ldmatrix gathers
#define CSWZ(r, c) ((((c) ^ (((r) >> 1) & 3))) << 4)
// unit swizzle for 128-byte rows (standard SW128): unit' = unit ^ (r & 7)
#define SWZ8(r, c) ((((c) ^ ((r) & 7))) << 4)

__device__ __forceinline__ uint32_t pack2h(float a, float b) {
    __half2 H{__float2half_rn(a), __float2half_rn(b)};
    return *(uint32_t*)&H;
}

// ---------------- fp32 -> fp16 single convert ----------------
__global__ __launch_bounds__(256) void cvt_fp16(const float* __restrict__ src,
                                                __half* __restrict__ dst, int n4) {
    int i = blockIdx.x * 256 + threadIdx.x;
    if (i >= n4) return;
    float4 v = ((const float4*)src)[i];
    ((uint32_t*)dst)[2 * i + 0] = pack2h(v.x, v.y);
    ((uint32_t*)dst)[2 * i + 1] = pack2h(v.z, v.w);
}

// ---------------- single fp16 HMMA GEMM: C = A @ B^T ----------------------
// k-tile = 64 (128-byte rows, SW128 swizzle). Stage: A 16K | B 16K = 32KB;
// 3 stages = 96KB, 2 CTAs/SM.
#define GM_SMEM (3 * 32768)

__global__ __launch_bounds__(256, 2) void gemm_mma_f16(const __half* __restrict__ Ah,
                                                       const __half* __restrict__ Bh,
                                                       float* __restrict__ C,
                                                       int M, int N, int K, int ldc) {
    extern __shared__ __align__(1024) char sm[];
    const int tid = threadIdx.x;
    const int m0 = blockIdx.y * 128, n0 = blockIdx.x * 128;
    const uint32_t sb0 = smem_u32(sm);
    const int warp = tid >> 5, lane = tid & 31;
    const int warp_m = warp & 3, warp_n = warp >> 2;
    const int KT = K >> 6;

    float acc[2][8][4];
#pragma unroll
    for (int a = 0; a < 2; a++)
#pragma unroll
        for (int b = 0; b < 8; b++)
#pragma unroll
            for (int c = 0; c < 4; c++) acc[a][b][c] = 0.f;

    auto load_stage = [&](int kt, int s) {
        const uint32_t sb = sb0 + s * 32768;
        const int k0 = kt << 6;
#pragma unroll
        for (int ii = 0; ii < 4; ii++) {
            const int i = tid + ii * 256;              // 1024 float4 per operand
            const int r = i >> 3, c = i & 7;
            const uint32_t sw = (uint32_t)(r * 128) + SWZ8(r, c);
            const size_t ga = (size_t)(m0 + r) * K + k0 + c * 8;
            cpasync16(sb + sw, Ah + ga, 16);
            const int rb = (n0 + r < N) ? (n0 + r) : (N - 1);
            const int bs = (n0 + r < N) ? 16 : 0;
            const size_t gb = (size_t)rb * K + k0 + c * 8;
            cpasync16(sb + 16384 + sw, Bh + gb, bs);
        }
    };

    load_stage(0, 0);
    CP_COMMIT();
    if (KT > 1) {
        load_stage(1, 1);
        CP_COMMIT();
    }

    const int lrow = (lane & 7) + ((lane >> 3) & 1) * 8;
    const int lhalf = lane >> 4;

    for (int kt = 0; kt < KT; kt++) {
        if (kt + 1 < KT) CP_WAIT1(); else CP_WAIT0();
        __syncthreads();
        if (kt + 2 < KT) {
            load_stage(kt + 2, (kt + 2) % 3);
            CP_COMMIT();
        }

        const uint32_t sb = sb0 + (kt % 3) * 32768;
#pragma unroll
        for (int ki = 0; ki < 4; ki++) {
            const int unit = ki * 2 + lhalf;           // 16-byte unit within 128-B row
            uint32_t ah[2][4];
#pragma unroll
            for (int mi = 0; mi < 2; mi++) {
                const int r = warp_m * 32 + mi * 16 + lrow;
                const uint32_t off = (uint32_t)(r * 128) + SWZ8(r, unit);
                ldm4(ah[mi], sb + off);
            }
            uint32_t bh[4][4];
#pragma unroll
            for (int nj = 0; nj < 4; nj++) {
                const int r = warp_n * 64 + nj * 16 + lrow;
                const uint32_t off = (uint32_t)(r * 128) + SWZ8(r, unit);
                ldm4(bh[nj], sb + 16384 + off);
            }
#pragma unroll
            for (int mi = 0; mi < 2; mi++)
#pragma unroll
                for (int nj = 0; nj < 8; nj++) {
                    const int g = nj >> 1, h = nj & 1;
                    mma16816h(acc[mi][nj], ah[mi], bh[g][h], bh[g][h + 2]);
                }
        }
    }

#pragma unroll
    for (int mi = 0; mi < 2; mi++)
#pragma unroll
        for (int nj = 0; nj < 8; nj++) {
            const int row = m0 + warp_m * 32 + mi * 16 + (lane >> 2);
            const int col = n0 + warp_n * 64 + nj * 8 + (lane & 3) * 2;
            if (col < N) {
                float2 v0 = make_float2(acc[mi][nj][0], acc[mi][nj][1]);
                float2 v1 = make_float2(acc[mi][nj][2], acc[mi][nj][3]);
                *(float2*)&C[(size_t)row * ldc + col] = v0;
                *(float2*)&C[(size_t)(row + 8) * ldc + col] = v1;
            }
        }
}

// ---------------- exact fp32 dt: softplus(u @ W_dt^T + bias) -------------
// 512 CTAs x 8 rows; W staged k-major (stride 33) -> conflict-free reads.
__global__ __launch_bounds__(256) void kernel_dt(const float* __restrict__ u,
                                                 const float* __restrict__ W_in,
                                                 const float* __restrict__ dtb) {
    __shared__ float ush[8 * 68];
    __shared__ float wsh[64 * 33];
    const int tid = threadIdx.x;
    const int row0 = blockIdx.x * 8;
    const int col = tid & 31, r0 = tid >> 5;   // one u row per thread
    float acc = 0.f;

    for (int k0 = 0; k0 < DM; k0 += 64) {
        if (tid < 128) {
            const int r = tid >> 4, c = (tid & 15) * 4;
            *(float4*)&ush[r * 68 + c] = *(const float4*)&u[(size_t)(row0 + r) * DM + k0 + c];
        }
#pragma unroll
        for (int ii = 0; ii < 2; ii++) {
            const int i = tid + ii * 256;
            const int r = i >> 4, c = (i & 15) * 4;
            float4 w = *(const float4*)&W_in[(size_t)(NZX + r) * DM + k0 + c];
            wsh[(c + 0) * 33 + r] = w.x;
            wsh[(c + 1) * 33 + r] = w.y;
            wsh[(c + 2) * 33 + r] = w.z;
            wsh[(c + 3) * 33 + r] = w.w;
        }
        __syncthreads();
#pragma unroll 8
        for (int k = 0; k < 64; k++)
            acc += ush[r0 * 68 + k] * wsh[k * 33 + col];
        __syncthreads();
    }
    float x = acc + dtb[col];
    g_dt[(row0 + r0) * NH + col] = (x > 20.f) ? x : log1pf(expf(x));
}

// ---------------- tree conv + silu ----------------
__global__ __launch_bounds__(256) void kernel_conv(const int* __restrict__ cidx,
                                                   const float* __restrict__ cw,
                                                   const float* __restrict__ cb) {
    const int bt = blockIdx.x;           // b*L_ + t
    const int b = bt / L_, t = bt - b * L_;
    const int tid = threadIdx.x;

    __shared__ int idx[4];
    if (tid < 4) idx[tid] = cidx[(size_t)b * 4 * L_ + 4 * t + tid];
    __syncthreads();
    const int i0 = idx[0], i1 = idx[1], i2 = idx[2], i3 = idx[3];

    for (int c = tid; c < CD; c += 256) {
        float acc = cb[c];
        const float* w = cw + c * 4;
        if (i0) acc += g_zx[(size_t)(b * L_ + i0 - 1) * NZX + DSSM + c] * w[0];
        if (i1) acc += g_zx[(size_t)(b * L_ + i1 - 1) * NZX + DSSM + c] * w[1];
        if (i2) acc += g_zx[(size_t)(b * L_ + i2 - 1) * NZX + DSSM + c] * w[2];
        if (i3) acc += g_zx[(size_t)(b * L_ + i3 - 1) * NZX + DSSM + c] * w[3];
        g_xBC[(size_t)bt * CD + c] = acc / (1.f + __expf(-acc));   // silu
    }
}

// ---------------- per-(b,c,h) inclusive cumsum of dt*A ----------------
__global__ __launch_bounds__(256) void kernel_cumA(const float* __restrict__ A_log) {
    const int blk = blockIdx.x;                 // (b*NC+c)*NH + h
    const int h = blk & (NH - 1);
    const int bc = blk / NH;
    const int b = bc / NC, c = bc - b * NC;
    const int t = threadIdx.x;
    const float Ah = -expf(A_log[h]);
    const int l = b * L_ + c * CH + t;
    __shared__ float s[CH];
    s[t] = g_dt[l * NH + h] * Ah;
    __syncthreads();
    for (int off = 1; off < CH; off <<= 1) {
        float add = (t >= off) ? s[t - off] : 0.f;
        __syncthreads();
        s[t] += add;
        __syncthreads();
    }
    g_cumA[blk * CH + t] = s[t];
}

// ---------------- G = C @ B^T per (b,chunk): lower-triangle blocks only --
__global__ void kernel_G() {
    const int bc = blockIdx.z;                 // b*NC + c
    const int t0 = blockIdx.y * 16, s0 = blockIdx.x * 16;
    if (t0 + 16 <= s0) return;                 // upper triangle never read
    const int tx = threadIdx.x, ty = threadIdx.y;
    const int tid = ty * 16 + tx;
    __shared__ float Cs[16][129];
    __shared__ float Bs[16][129];
    const int b = bc / NC, c = bc - b * NC;
    const int base_l = b * L_ + c * CH;
    for (int i = tid; i < 16 * 128; i += 256) {
        int row = i >> 7, n = i & 127;
        Cs[row][n] = g_xBC[(size_t)(base_l + t0 + row) * CD + DSSM + DS + n];
        Bs[row][n] = g_xBC[(size_t)(base_l + s0 + row) * CD + DSSM + n];
    }
    __syncthreads();
    float acc = 0.f;
#pragma unroll 8
    for (int n = 0; n < 128; n++) acc += Cs[ty][n] * Bs[tx][n];
    g_G[((size_t)bc * CH + t0 + ty) * CH + s0 + tx] = acc;
}

// ---------------- states on fp16 HMMA: S[p,n] = sum_s ws[s]*x[s,p]*B[s,n]
// Both operands single fp16. 1 MMA per pair.
#define ST_CUMA 0
#define ST_WS   1024
#define ST_A    2048                     // 4KB
#define ST_B    6144                     // 8KB
#define ST_BSTG 14336                    // [32][129] fp32 = 16512 B
#define ST_XSTG 30848                    // [32][65]  fp32 = 8320 B
#define ST_SMEM 39168

__global__ __launch_bounds__(256) void kernel_states_mma() {
    extern __shared__ __align__(1024) char sm[];
    const int blk = blockIdx.x;
    const int h = blk & (NH - 1);
    const int bc = blk / NH;
    const int b = bc / NC, c = bc - b * NC;
    const int tid = threadIdx.x;
    const int base_l = b * L_ + c * CH;
    const uint32_t sb = smem_u32(sm);
    float* cumA_sh = (float*)(sm + ST_CUMA);
    float* ws_sh = (float*)(sm + ST_WS);
    float* Bstg = (float*)(sm + ST_BSTG);
    float* xstg = (float*)(sm + ST_XSTG);

    cumA_sh[tid] = g_cumA[blk * CH + tid];
    __syncthreads();
    ws_sh[tid] = g_dt[(base_l + tid) * NH + h] * __expf(cumA_sh[CH - 1] - cumA_sh[tid]);
    __syncthreads();

    const int warp = tid >> 5, lane = tid & 31;
    const int warp_m = warp & 1, warp_n = warp >> 1;
    const int lrow = (lane & 7) + ((lane >> 3) & 1) * 8;
    const int lhalf = lane >> 4;

    float acc[2][4][4];
#pragma unroll
    for (int a = 0; a < 2; a++)
#pragma unroll
        for (int bq = 0; bq < 4; bq++)
#pragma unroll
            for (int cq = 0; cq < 4; cq++) acc[a][bq][cq] = 0.f;

    for (int s0 = 0; s0 < CH; s0 += 32) {
#pragma unroll
        for (int ii = 0; ii < 16; ii++) {
            const int i = tid + ii * 256;
            const int s = i >> 7, n = i & 127;
            Bstg[s * 129 + n] = g_xBC[(size_t)(base_l + s0 + s) * CD + DSSM + n];
        }
#pragma unroll
        for (int ii = 0; ii < 8; ii++) {
            const int i = tid + ii * 256;
            const int s = i >> 6, p = i & 63;
            xstg[s * 65 + p] = g_xBC[(size_t)(base_l + s0 + s) * CD + h * HD + p];
        }
        __syncthreads();
#pragma unroll
        for (int jj = 0; jj < 8; jj++) {
            const int j = tid + jj * 256;              // 2048
            const int n = j >> 4, sl = (j & 15) * 2;
            const uint32_t a = (uint32_t)(n * 64) + CSWZ(n, sl >> 3) + (sl & 7) * 2;
            *(uint32_t*)(sm + ST_B + a) = pack2h(Bstg[sl * 129 + n], Bstg[(sl + 1) * 129 + n]);
        }
#pragma unroll
        for (int jj = 0; jj < 4; jj++) {
            const int j = tid + jj * 256;              // 1024
            const int p = j >> 4, sl = (j & 15) * 2;
            const uint32_t a = (uint32_t)(p * 64) + CSWZ(p, sl >> 3) + (sl & 7) * 2;
            *(uint32_t*)(sm + ST_A + a) =
                pack2h(xstg[sl * 65 + p] * ws_sh[s0 + sl],
                       xstg[(sl + 1) * 65 + p] * ws_sh[s0 + sl + 1]);
        }
        __syncthreads();
#pragma unroll
        for (int ki = 0; ki < 2; ki++) {
            const int chunk = ki * 2 + lhalf;
            uint32_t ah[2][4];
#pragma unroll
            for (int mi = 0; mi < 2; mi++) {
                const int r = warp_m * 32 + mi * 16 + lrow;
                const uint32_t off = (uint32_t)(r * 64) + CSWZ(r, chunk);
                ldm4(ah[mi], sb + ST_A + off);
            }
            uint32_t bh[2][4];
#pragma unroll
            for (int nj = 0; nj < 2; nj++) {
                const int r = warp_n * 32 + nj * 16 + lrow;
                const uint32_t off = (uint32_t)(r * 64) + CSWZ(r, chunk);
                ldm4(bh[nj], sb + ST_B + off);
            }
#pragma unroll
            for (int mi = 0; mi < 2; mi++)
#pragma unroll
                for (int nj = 0; nj < 4; nj++) {
                    const int g = nj >> 1, hh = nj & 1;
                    mma16816h(acc[mi][nj], ah[mi], bh[g][hh], bh[g][hh + 2]);
                }
        }
        __syncthreads();
    }

#pragma unroll
    for (int mi = 0; mi < 2; mi++)
#pragma unroll
        for (int nj = 0; nj < 4; nj++) {
            const int row = warp_m * 32 + mi * 16 + (lane >> 2);
            const int col = warp_n * 32 + nj * 8 + (lane & 3) * 2;
            float* dst = &g_states[(size_t)blk * HD * DS + (size_t)row * DS + col];
            *(float2*)dst = make_float2(acc[mi][nj][0], acc[mi][nj][1]);
            *(float2*)(dst + 8 * DS) = make_float2(acc[mi][nj][2], acc[mi][nj][3]);
        }
}

// ---------------- inter-chunk recurrence (sequential over chunks) --------
__global__ __launch_bounds__(256) void kernel_scan() {
    const int b = blockIdx.x >> 5;
    const int h = blockIdx.x & 31;
    const int tid = threadIdx.x;
    float4 prev[8];
#pragma unroll
    for (int i = 0; i < 8; i++) prev[i] = make_float4(0.f, 0.f, 0.f, 0.f);
    for (int c = 0; c < NC; c++) {
        int blk = (b * NC + c) * NH + h;
        float cd = __expf(g_cumA[blk * CH + CH - 1]);
        const float4* st = (const float4*)&g_states[(size_t)blk * HD * DS];
        float4* pv = (float4*)&g_prev[(size_t)blk * HD * DS];
#pragma unroll
        for (int i = 0; i < 8; i++) {
            float4 s = st[tid + i * 256];
            float4 pr = prev[i];
            pv[tid + i * 256] = pr;
            prev[i] = make_float4(pr.x * cd + s.x, pr.y * cd + s.y,
                                  pr.z * cd + s.z, pr.w * cd + s.w);
        }
    }
}

// ---------------- fused Yd + Yoff + D*x on fp16 HMMA ---------------------
// Both operands single fp16. 1 MMA per pair.
#define YO_CUMA  0
#define YO_DT    1024
#define YO_EA    2048
#define YO_W     3072                    // 16KB [256][64B]
#define YO_XT    19456                   // 4KB [64][64B]
#define YO_STAGE 23552                   // [32][65] fp32 = 8320 B
#define YO_SMEM  31872

__global__ __launch_bounds__(256) void kernel_ydoff_mma(const float* __restrict__ Dv) {
    extern __shared__ __align__(1024) char sm[];
    const int blk = blockIdx.x;
    const int h = blk & (NH - 1);
    const int bc = blk / NH;
    const int b = bc / NC, c = bc - b * NC;
    const int tid = threadIdx.x;
    const int base_l = b * L_ + c * CH;
    const uint32_t sb = smem_u32(sm);
    float* cumA_sh = (float*)(sm + YO_CUMA);
    float* dt_sh = (float*)(sm + YO_DT);
    float* eA_sh = (float*)(sm + YO_EA);
    float* stg = (float*)(sm + YO_STAGE);
    const float* Gb = g_G + (size_t)bc * CH * CH;

    cumA_sh[tid] = g_cumA[blk * CH + tid];
    dt_sh[tid] = g_dt[(base_l + tid) * NH + h];
    __syncthreads();
    eA_sh[tid] = __expf(cumA_sh[tid]);
    __syncthreads();

    const int warp = tid >> 5, lane = tid & 31;
    const int lrow = (lane & 7) + ((lane >> 3) & 1) * 8;
    const int lhalf = lane >> 4;
    const int rb0 = warp * 16;
    const int rb1 = 240 - warp * 16;

    float acc[2][8][4];
#pragma unroll
    for (int a = 0; a < 2; a++)
#pragma unroll
        for (int bq = 0; bq < 8; bq++)
#pragma unroll
            for (int cq = 0; cq < 4; cq++) acc[a][bq][cq] = 0.f;

    // ---- phase 1: Yd over s-chunks (triangular) ----
    for (int s0 = 0; s0 < CH; s0 += 32) {
#pragma unroll
        for (int ii = 0; ii < 8; ii++) {
            const int i = tid + ii * 256;
            const int s = i >> 6, p = i & 63;
            stg[s * 65 + p] = g_xBC[(size_t)(base_l + s0 + s) * CD + h * HD + p];
        }
        __syncthreads();
        const int nent = (CH - s0) * 16;
        for (int j = tid; j < nent; j += 256) {
            const int t = s0 + (j >> 4), sl = (j & 15) * 2;
            const int sg = s0 + sl;
            const float cat = cumA_sh[t];
            float w0 = (t >= sg) ? Gb[t * CH + sg] * __expf(cat - cumA_sh[sg]) * dt_sh[sg] : 0.f;
            float w1 = (t >= sg + 1) ? Gb[t * CH + sg + 1] * __expf(cat - cumA_sh[sg + 1]) * dt_sh[sg + 1] : 0.f;
            const uint32_t a = (uint32_t)(t * 64) + CSWZ(t, sl >> 3) + (sl & 7) * 2;
            *(uint32_t*)(sm + YO_W + a) = pack2h(w0, w1);
        }
#pragma unroll
        for (int jj = 0; jj < 4; jj++) {
            const int j = tid + jj * 256;              // 1024
            const int p = j >> 4, sl = (j & 15) * 2;
            const uint32_t a = (uint32_t)(p * 64) + CSWZ(p, sl >> 3) + (sl & 7) * 2;
            *(uint32_t*)(sm + YO_XT + a) = pack2h(stg[sl * 65 + p], stg[(sl + 1) * 65 + p]);
        }
        __syncthreads();
        const bool act0 = (rb0 + 16 > s0);
        const bool act1 = (rb1 + 16 > s0);
        if (act0 || act1) {
#pragma unroll
            for (int ki = 0; ki < 2; ki++) {
                const int chunk = ki * 2 + lhalf;
                uint32_t bh[4][4];
#pragma unroll
                for (int nj = 0; nj < 4; nj++) {
                    const int r = nj * 16 + lrow;
                    const uint32_t off = (uint32_t)(r * 64) + CSWZ(r, chunk);
                    ldm4(bh[nj], sb + YO_XT + off);
                }
#pragma unroll
                for (int mi = 0; mi < 2; mi++) {
                    if (mi == 0 ? !act0 : !act1) continue;
                    const int r = (mi ? rb1 : rb0) + lrow;
                    const uint32_t off = (uint32_t)(r * 64) + CSWZ(r, chunk);
                    uint32_t ah[4];
                    ldm4(ah, sb + YO_W + off);
#pragma unroll
                    for (int nj = 0; nj < 8; nj++) {
                        const int g = nj >> 1, hh = nj & 1;
                        mma16816h(acc[mi][nj], ah, bh[g][hh], bh[g][hh + 2]);
                    }
                }
            }
        }
        __syncthreads();
    }

    // ---- phase 2: Yoff over n-chunks (dense) ----
    const float* prev_base = &g_prev[(size_t)blk * HD * DS];
    for (int n0 = 0; n0 < DS; n0 += 32) {
#pragma unroll
        for (int jj = 0; jj < 16; jj++) {
            const int j = tid + jj * 256;              // 4096
            const int t = j >> 4, nl = (j & 15) * 2;
            const float ea = eA_sh[t];
            const float* cp = &g_xBC[(size_t)(base_l + t) * CD + DSSM + DS + n0 + nl];
            const uint32_t a = (uint32_t)(t * 64) + CSWZ(t, nl >> 3) + (nl & 7) * 2;
            *(uint32_t*)(sm + YO_W + a) = pack2h(cp[0] * ea, cp[1] * ea);
        }
#pragma unroll
        for (int jj = 0; jj < 4; jj++) {
            const int j = tid + jj * 256;              // 1024
            const int p = j >> 4, nl = (j & 15) * 2;
            const float* pp = &prev_base[(size_t)p * DS + n0 + nl];
            const uint32_t a = (uint32_t)(p * 64) + CSWZ(p, nl >> 3) + (nl & 7) * 2;
            *(uint32_t*)(sm + YO_XT + a) = pack2h(pp[0], pp[1]);
        }
        __syncthreads();
#pragma unroll
        for (int ki = 0; ki < 2; ki++) {
            const int chunk = ki * 2 + lhalf;
            uint32_t bh[4][4];
#pragma unroll
            for (int nj = 0; nj < 4; nj++) {
                const int r = nj * 16 + lrow;
                const uint32_t off = (uint32_t)(r * 64) + CSWZ(r, chunk);
                ldm4(bh[nj], sb + YO_XT + off);
            }
#pragma unroll
            for (int mi = 0; mi < 2; mi++) {
                const int r = (mi ? rb1 : rb0) + lrow;
                const uint32_t off = (uint32_t)(r * 64) + CSWZ(r, chunk);
                uint32_t ah[4];
                ldm4(ah, sb + YO_W + off);
#pragma unroll
                for (int nj = 0; nj < 8; nj++) {
                    const int g = nj >> 1, hh = nj & 1;
                    mma16816h(acc[mi][nj], ah, bh[g][hh], bh[g][hh + 2]);
                }
            }
        }
        __syncthreads();
    }

    // ---- epilogue: + D[h]*x, write Y ----
    const float Dh = Dv[h];
#pragma unroll
    for (int mi = 0; mi < 2; mi++)
#pragma unroll
        for (int nj = 0; nj < 8; nj++) {
            const int row = (mi ? rb1 : rb0) + (lane >> 2);
            const int col = nj * 8 + (lane & 3) * 2;
            const size_t l0 = (size_t)(base_l + row);
            float2 x0 = *(const float2*)&g_xBC[l0 * CD + h * HD + col];
            float2 x1 = *(const float2*)&g_xBC[(l0 + 8) * CD + h * HD + col];
            *(float2*)&g_Y[l0 * DSSM + h * HD + col] =
                make_float2(acc[mi][nj][0] + Dh * x0.x, acc[mi][nj][1] + Dh * x0.y);
            *(float2*)&g_Y[(l0 + 8) * DSSM + h * HD + col] =
                make_float2(acc[mi][nj][2] + Dh * x1.x, acc[mi][nj][3] + Dh * x1.y);
        }
}

// ---------------- gated RMSNorm -> single fp16 ----------------
__global__ __launch_bounds__(256) void kernel_norm(const float* __restrict__ nw) {
    const int row = blockIdx.x;
    const int tid = threadIdx.x;
    const float* y = &g_Y[(size_t)row * DSSM];
    const float* z = &g_zx[(size_t)row * NZX];  // z = first DSSM cols
    float v[8];
    float sum = 0.f;
#pragma unroll
    for (int i = 0; i < 8; i++) {
        int cc = tid + i * 256;
        float zz = z[cc];
        float vv = y[cc] * (zz / (1.f + __expf(-zz)));
        v[i] = vv;
        sum += vv * vv;
    }
    __shared__ float red[256];
    red[tid] = sum;
    __syncthreads();
    for (int off = 128; off; off >>= 1) {
        if (tid < off) red[tid] += red[tid + off];
        __syncthreads();
    }
    const float scale = rsqrtf(red[0] * (1.f / DSSM) + 1e-5f);
#pragma unroll
    for (int i = 0; i < 8; i++) {
        int cc = tid + i * 256;
        g_ynh[(size_t)row * DSSM + cc] = __float2half_rn(v[i] * scale * nw[cc]);
    }
}

// ---------------- launch ----------------
extern "C" void kernel_launch(void* const* d_in, const int* in_sizes, int n_in,
                              void* d_out, int out_size) {
    const float* u     = (const float*)d_in[0];
    const int*   cidx  = (const int*)d_in[1];
    const float* W_in  = (const float*)d_in[2];
    const float* cw    = (const float*)d_in[3];
    const float* cb    = (const float*)d_in[4];
    const float* dtb   = (const float*)d_in[5];
    const float* A_log = (const float*)d_in[6];
    const float* Dv    = (const float*)d_in[7];
    const float* nw    = (const float*)d_in[8];
    const float* W_out = (const float*)d_in[9];
    float* out = (float*)d_out;

    float* zx_p;
    __half *uh, *wih, *woh, *ynh;
    cudaGetSymbolAddress((void**)&zx_p, g_zx);
    cudaGetSymbolAddress((void**)&uh, g_uh);
    cudaGetSymbolAddress((void**)&wih, g_wih);
    cudaGetSymbolAddress((void**)&woh, g_woh);
    cudaGetSymbolAddress((void**)&ynh, g_ynh);

    cudaFuncSetAttribute(gemm_mma_f16, cudaFuncAttributeMaxDynamicSharedMemorySize, GM_SMEM);
    cudaFuncSetAttribute(kernel_states_mma, cudaFuncAttributeMaxDynamicSharedMemorySize, ST_SMEM);
    cudaFuncSetAttribute(kernel_ydoff_mma, cudaFuncAttributeMaxDynamicSharedMemorySize, YO_SMEM);

    // 0) operand converts + exact fp32 dt (conflict-free W staging)
    {
        int n4;
        n4 = (B_ * L_ * DM) / 4;
        cvt_fp16<<<(n4 + 255) / 256, 256>>>(u, uh, n4);
        n4 = (DIP * DM) / 4;
        cvt_fp16<<<(n4 + 255) / 256, 256>>>(W_in, wih, n4);
        n4 = (DM * DSSM) / 4;
        cvt_fp16<<<(n4 + 255) / 256, 256>>>(W_out, woh, n4);
        kernel_dt<<<(B_ * L_) / 8, 256>>>(u, W_in, dtb);
    }
    // 1) z|xBC = u @ W_in[0:4352]^T   (M=4096, N=4352, K=1024) on fp16 HMMA
    gemm_mma_f16<<<dim3(NZX / 128, (B_ * L_) / 128), 256, GM_SMEM>>>(
        uh, wih, zx_p, B_ * L_, NZX, DM, NZX);
    // 2) tree conv + silu
    kernel_conv<<<B_ * L_, 256>>>(cidx, cw, cb);
    // 3) cumsum(dt*A) per chunk/head
    kernel_cumA<<<B_ * NC * NH, 256>>>(A_log);
    // 4) G = C@B^T per (b,chunk), lower-triangle blocks only
    kernel_G<<<dim3(CH / 16, CH / 16, B_ * NC), dim3(16, 16)>>>();
    // 5) chunk end-states on fp16 HMMA (single fp16)
    kernel_states_mma<<<B_ * NC * NH, 256, ST_SMEM>>>();
    // 6) inter-chunk scan
    kernel_scan<<<B_ * NH, 256>>>();
    // 7) fused Yd + Yoff + D*x on fp16 HMMA (single fp16, triangular skip)
    kernel_ydoff_mma<<<B_ * NC * NH, 256, YO_SMEM>>>(Dv);
    // 8) gated RMSNorm -> single fp16
    kernel_norm<<<B_ * L_, 256>>>(nw);
    // 9) out = yn @ W_out^T  (M=4096, N=1024, K=2048) on fp16 HMMA
    gemm_mma_f16<<<dim3(DM / 128, (B_ * L_) / 128), 256, GM_SMEM>>>(
        ynh, woh, out, B_ * L_, DM, DSSM, DM);
}

// round 14
// speedup vs baseline: 1.1083x; 1.1083x over previous
#include <cuda_runtime.h>
#include <cuda_bf16.h>
#include <cuda_fp16.h>
#include <math.h>
#include <stdint.h>

#define B_   2
#define L_   2048
#define DM   1024
#define DIP  4384
#define DSSM 2048
#define CD   2304
#define NZX  (DSSM + CD)               /* 4352 = z | xBC, dt handled separately */
#define NH   32
#define HD   64
#define DS   128
#define CH   256
#define NC   8

// ---------------- scratch (device globals; no allocation) ----------------
__device__ float g_zx[B_ * L_ * NZX];          // in-proj output (z | xBC)
__device__ float g_xBC[B_ * L_ * CD];          // post-conv+silu (x | B | C)
__device__ float g_dt[B_ * L_ * NH];           // softplus dt (computed in fp32)
__device__ float g_G[B_ * NC * CH * CH];       // per-chunk C@B^T (head-independent)
__device__ float g_cumA[B_ * NC * NH * CH];    // inclusive cumsum of dt*A per chunk
__device__ float g_states[B_ * NC * NH * HD * DS];
__device__ float g_prev[B_ * NC * NH * HD * DS];
__device__ float g_Y[B_ * L_ * DSSM];

// fp16 operand buffers for the two projection GEMMs
__device__ __half g_uh[B_ * L_ * DM];
__device__ __half g_wih[DIP * DM];             // W_in single fp16
__device__ __half g_woh[DM * DSSM];            // W_out single fp16
__device__ __half g_ynh[B_ * L_ * DSSM];

// ---------------- warp-level MMA helpers (arch-neutral PTX) ----------------
__device__ __forceinline__ uint32_t smem_u32(const void* p) {
    uint32_t a;
    asm("{ .reg .u64 t; cvta.to.shared.u64 t, %1; cvt.u32.u64 %0, t; }" : "=r"(a) : "l"(p));
    return a;
}
__device__ __forceinline__ void ldm4(uint32_t* r, uint32_t addr) {
    asm volatile("ldmatrix.sync.aligned.m8n8.x4.shared.b16 {%0,%1,%2,%3}, [%4];"
                 : "=r"(r[0]), "=r"(r[1]), "=r"(r[2]), "=r"(r[3]) : "r"(addr));
}
__device__ __forceinline__ void mma16816h(float* d, const uint32_t* a,
                                          uint32_t b0, uint32_t b1) {
    asm volatile(
        "mma.sync.aligned.m16n8k16.row.col.f32.f16.f16.f32 "
        "{%0,%1,%2,%3}, {%4,%5,%6,%7}, {%8,%9}, {%0,%1,%2,%3};"
        : "+f"(d[0]), "+f"(d[1]), "+f"(d[2]), "+f"(d[3])
        : "r"(a[0]), "r"(a[1]), "r"(a[2]), "r"(a[3]), "r"(b0), "r"(b1));
}
__device__ __forceinline__ void cpasync16(uint32_t dst, const void* src, int sz) {
    asm volatile("cp.async.cg.shared.global [%0], [%1], 16, %2;"
                 :: "r"(dst), "l"(src), "r"(sz) : "memory");
}
#define CP_COMMIT() asm volatile("cp.async.commit_group;" ::: "memory")
#define CP_WAIT0()  asm volatile("cp.async.wait_group 0;" ::: "memory")
#define CP_WAIT1()  asm volatile("cp.async.wait_group 1;" ::: "memory")

// chunk swizzle for 64-byte rows: conflict-free 8-row ldmatrix gathers
#define CSWZ(r, c) ((((c) ^ (((r) >> 1) & 3))) << 4)
// unit swizzle for 128-byte rows (standard SW128): unit' = unit ^ (r & 7)
#define SWZ8(r, c) ((((c) ^ ((r) & 7))) << 4)

__device__ __forceinline__ uint32_t pack2h(float a, float b) {
    __half2 H{__float2half_rn(a), __float2half_rn(b)};
    return *(uint32_t*)&H;
}

// ---------------- fp32 -> fp16 single convert ----------------
__global__ __launch_bounds__(256) void cvt_fp16(const float* __restrict__ src,
                                                __half* __restrict__ dst, int n4) {
    int i = blockIdx.x * 256 + threadIdx.x;
    if (i >= n4) return;
    float4 v = ((const float4*)src)[i];
    ((uint32_t*)dst)[2 * i + 0] = pack2h(v.x, v.y);
    ((uint32_t*)dst)[2 * i + 1] = pack2h(v.z, v.w);
}

// ---------------- single fp16 HMMA GEMM: C = A @ B^T ----------------------
// k-tile = 64 (128-byte rows, SW128 swizzle). Stage: A 16K | B 16K = 32KB;
// 3 stages = 96KB, 2 CTAs/SM.
#define GM_SMEM (3 * 32768)

__global__ __launch_bounds__(256, 2) void gemm_mma_f16(const __half* __restrict__ Ah,
                                                       const __half* __restrict__ Bh,
                                                       float* __restrict__ C,
                                                       int M, int N, int K, int ldc) {
    extern __shared__ __align__(1024) char sm[];
    const int tid = threadIdx.x;
    const int m0 = blockIdx.y * 128, n0 = blockIdx.x * 128;
    const uint32_t sb0 = smem_u32(sm);
    const int warp = tid >> 5, lane = tid & 31;
    const int warp_m = warp & 3, warp_n = warp >> 2;
    const int KT = K >> 6;

    float acc[2][8][4];
#pragma unroll
    for (int a = 0; a < 2; a++)
#pragma unroll
        for (int b = 0; b < 8; b++)
#pragma unroll
            for (int c = 0; c < 4; c++) acc[a][b][c] = 0.f;

    auto load_stage = [&](int kt, int s) {
        const uint32_t sb = sb0 + s * 32768;
        const int k0 = kt << 6;
#pragma unroll
        for (int ii = 0; ii < 4; ii++) {
            const int i = tid + ii * 256;              // 1024 float4 per operand
            const int r = i >> 3, c = i & 7;
            const uint32_t sw = (uint32_t)(r * 128) + SWZ8(r, c);
            const size_t ga = (size_t)(m0 + r) * K + k0 + c * 8;
            cpasync16(sb + sw, Ah + ga, 16);
            const int rb = (n0 + r < N) ? (n0 + r) : (N - 1);
            const int bs = (n0 + r < N) ? 16 : 0;
            const size_t gb = (size_t)rb * K + k0 + c * 8;
            cpasync16(sb + 16384 + sw, Bh + gb, bs);
        }
    };

    load_stage(0, 0);
    CP_COMMIT();
    if (KT > 1) {
        load_stage(1, 1);
        CP_COMMIT();
    }

    const int lrow = (lane & 7) + ((lane >> 3) & 1) * 8;
    const int lhalf = lane >> 4;

    for (int kt = 0; kt < KT; kt++) {
        if (kt + 1 < KT) CP_WAIT1(); else CP_WAIT0();
        __syncthreads();
        if (kt + 2 < KT) {
            load_stage(kt + 2, (kt + 2) % 3);
            CP_COMMIT();
        }

        const uint32_t sb = sb0 + (kt % 3) * 32768;
#pragma unroll
        for (int ki = 0; ki < 4; ki++) {
            const int unit = ki * 2 + lhalf;           // 16-byte unit within 128-B row
            uint32_t ah[2][4];
#pragma unroll
            for (int mi = 0; mi < 2; mi++) {
                const int r = warp_m * 32 + mi * 16 + lrow;
                const uint32_t off = (uint32_t)(r * 128) + SWZ8(r, unit);
                ldm4(ah[mi], sb + off);
            }
            uint32_t bh[4][4];
#pragma unroll
            for (int nj = 0; nj < 4; nj++) {
                const int r = warp_n * 64 + nj * 16 + lrow;
                const uint32_t off = (uint32_t)(r * 128) + SWZ8(r, unit);
                ldm4(bh[nj], sb + 16384 + off);
            }
#pragma unroll
            for (int mi = 0; mi < 2; mi++)
#pragma unroll
                for (int nj = 0; nj < 8; nj++) {
                    const int g = nj >> 1, h = nj & 1;
                    mma16816h(acc[mi][nj], ah[mi], bh[g][h], bh[g][h + 2]);
                }
        }
    }

#pragma unroll
    for (int mi = 0; mi < 2; mi++)
#pragma unroll
        for (int nj = 0; nj < 8; nj++) {
            const int row = m0 + warp_m * 32 + mi * 16 + (lane >> 2);
            const int col = n0 + warp_n * 64 + nj * 8 + (lane & 3) * 2;
            if (col < N) {
                float2 v0 = make_float2(acc[mi][nj][0], acc[mi][nj][1]);
                float2 v1 = make_float2(acc[mi][nj][2], acc[mi][nj][3]);
                *(float2*)&C[(size_t)row * ldc + col] = v0;
                *(float2*)&C[(size_t)(row + 8) * ldc + col] = v1;
            }
        }
}

// ---------------- exact fp32 dt: softplus(u @ W_dt^T + bias) -------------
// 256 CTAs x 16 rows (proven R11 configuration).
__global__ __launch_bounds__(256) void kernel_dt(const float* __restrict__ u,
                                                 const float* __restrict__ W_in,
                                                 const float* __restrict__ dtb) {
    __shared__ float ush[16 * 68];
    __shared__ float wsh[32 * 68];
    const int tid = threadIdx.x;
    const int row0 = blockIdx.x * 16;
    const int col = tid & 31, r0 = (tid >> 5) * 2;
    float acc[2] = {0.f, 0.f};

    for (int k0 = 0; k0 < DM; k0 += 64) {
        {
            const int i = tid;                       // 256 = 16*16
            const int r = i >> 4, c = (i & 15) * 4;
            *(float4*)&ush[r * 68 + c] = *(const float4*)&u[(size_t)(row0 + r) * DM + k0 + c];
        }
#pragma unroll
        for (int ii = 0; ii < 2; ii++) {
            const int i = tid + ii * 256;
            const int r = i >> 4, c = (i & 15) * 4;
            *(float4*)&wsh[r * 68 + c] =
                *(const float4*)&W_in[(size_t)(NZX + r) * DM + k0 + c];
        }
        __syncthreads();
#pragma unroll 8
        for (int k = 0; k < 64; k++) {
            const float w = wsh[col * 68 + k];
            acc[0] += ush[(r0 + 0) * 68 + k] * w;
            acc[1] += ush[(r0 + 1) * 68 + k] * w;
        }
        __syncthreads();
    }
    const float bias = dtb[col];
#pragma unroll
    for (int j = 0; j < 2; j++) {
        float x = acc[j] + bias;
        g_dt[(row0 + r0 + j) * NH + col] = (x > 20.f) ? x : log1pf(expf(x));
    }
}

// ---------------- tree conv + silu ----------------
__global__ __launch_bounds__(256) void kernel_conv(const int* __restrict__ cidx,
                                                   const float* __restrict__ cw,
                                                   const float* __restrict__ cb) {
    const int bt = blockIdx.x;           // b*L_ + t
    const int b = bt / L_, t = bt - b * L_;
    const int tid = threadIdx.x;

    __shared__ int idx[4];
    if (tid < 4) idx[tid] = cidx[(size_t)b * 4 * L_ + 4 * t + tid];
    __syncthreads();
    const int i0 = idx[0], i1 = idx[1], i2 = idx[2], i3 = idx[3];

    for (int c = tid; c < CD; c += 256) {
        float acc = cb[c];
        const float* w = cw + c * 4;
        if (i0) acc += g_zx[(size_t)(b * L_ + i0 - 1) * NZX + DSSM + c] * w[0];
        if (i1) acc += g_zx[(size_t)(b * L_ + i1 - 1) * NZX + DSSM + c] * w[1];
        if (i2) acc += g_zx[(size_t)(b * L_ + i2 - 1) * NZX + DSSM + c] * w[2];
        if (i3) acc += g_zx[(size_t)(b * L_ + i3 - 1) * NZX + DSSM + c] * w[3];
        g_xBC[(size_t)bt * CD + c] = acc / (1.f + __expf(-acc));   // silu
    }
}

// ---------------- per-(b,c,h) inclusive cumsum of dt*A ----------------
__global__ __launch_bounds__(256) void kernel_cumA(const float* __restrict__ A_log) {
    const int blk = blockIdx.x;                 // (b*NC+c)*NH + h
    const int h = blk & (NH - 1);
    const int bc = blk / NH;
    const int b = bc / NC, c = bc - b * NC;
    const int t = threadIdx.x;
    const float Ah = -expf(A_log[h]);
    const int l = b * L_ + c * CH + t;
    __shared__ float s[CH];
    s[t] = g_dt[l * NH + h] * Ah;
    __syncthreads();
    for (int off = 1; off < CH; off <<= 1) {
        float add = (t >= off) ? s[t - off] : 0.f;
        __syncthreads();
        s[t] += add;
        __syncthreads();
    }
    g_cumA[blk * CH + t] = s[t];
}

// ---------------- G = C @ B^T per (b,chunk): lower-triangle blocks only --
__global__ void kernel_G() {
    const int bc = blockIdx.z;                 // b*NC + c
    const int t0 = blockIdx.y * 16, s0 = blockIdx.x * 16;
    if (t0 + 16 <= s0) return;                 // upper triangle never read
    const int tx = threadIdx.x, ty = threadIdx.y;
    const int tid = ty * 16 + tx;
    __shared__ float Cs[16][129];
    __shared__ float Bs[16][129];
    const int b = bc / NC, c = bc - b * NC;
    const int base_l = b * L_ + c * CH;
    for (int i = tid; i < 16 * 128; i += 256) {
        int row = i >> 7, n = i & 127;
        Cs[row][n] = g_xBC[(size_t)(base_l + t0 + row) * CD + DSSM + DS + n];
        Bs[row][n] = g_xBC[(size_t)(base_l + s0 + row) * CD + DSSM + n];
    }
    __syncthreads();
    float acc = 0.f;
#pragma unroll 8
    for (int n = 0; n < 128; n++) acc += Cs[ty][n] * Bs[tx][n];
    g_G[((size_t)bc * CH + t0 + ty) * CH + s0 + tx] = acc;
}

// ---------------- states on fp16 HMMA: S[p,n] = sum_s ws[s]*x[s,p]*B[s,n]
// Both operands single fp16. 1 MMA per pair.
#define ST_CUMA 0
#define ST_WS   1024
#define ST_A    2048                     // 4KB
#define ST_B    6144                     // 8KB
#define ST_BSTG 14336                    // [32][129] fp32 = 16512 B
#define ST_XSTG 30848                    // [32][65]  fp32 = 8320 B
#define ST_SMEM 39168

__global__ __launch_bounds__(256) void kernel_states_mma() {
    extern __shared__ __align__(1024) char sm[];
    const int blk = blockIdx.x;
    const int h = blk & (NH - 1);
    const int bc = blk / NH;
    const int b = bc / NC, c = bc - b * NC;
    const int tid = threadIdx.x;
    const int base_l = b * L_ + c * CH;
    const uint32_t sb = smem_u32(sm);
    float* cumA_sh = (float*)(sm + ST_CUMA);
    float* ws_sh = (float*)(sm + ST_WS);
    float* Bstg = (float*)(sm + ST_BSTG);
    float* xstg = (float*)(sm + ST_XSTG);

    cumA_sh[tid] = g_cumA[blk * CH + tid];
    __syncthreads();
    ws_sh[tid] = g_dt[(base_l + tid) * NH + h] * __expf(cumA_sh[CH - 1] - cumA_sh[tid]);
    __syncthreads();

    const int warp = tid >> 5, lane = tid & 31;
    const int warp_m = warp & 1, warp_n = warp >> 1;
    const int lrow = (lane & 7) + ((lane >> 3) & 1) * 8;
    const int lhalf = lane >> 4;

    float acc[2][4][4];
#pragma unroll
    for (int a = 0; a < 2; a++)
#pragma unroll
        for (int bq = 0; bq < 4; bq++)
#pragma unroll
            for (int cq = 0; cq < 4; cq++) acc[a][bq][cq] = 0.f;

    for (int s0 = 0; s0 < CH; s0 += 32) {
#pragma unroll
        for (int ii = 0; ii < 16; ii++) {
            const int i = tid + ii * 256;
            const int s = i >> 7, n = i & 127;
            Bstg[s * 129 + n] = g_xBC[(size_t)(base_l + s0 + s) * CD + DSSM + n];
        }
#pragma unroll
        for (int ii = 0; ii < 8; ii++) {
            const int i = tid + ii * 256;
            const int s = i >> 6, p = i & 63;
            xstg[s * 65 + p] = g_xBC[(size_t)(base_l + s0 + s) * CD + h * HD + p];
        }
        __syncthreads();
#pragma unroll
        for (int jj = 0; jj < 8; jj++) {
            const int j = tid + jj * 256;              // 2048
            const int n = j >> 4, sl = (j & 15) * 2;
            const uint32_t a = (uint32_t)(n * 64) + CSWZ(n, sl >> 3) + (sl & 7) * 2;
            *(uint32_t*)(sm + ST_B + a) = pack2h(Bstg[sl * 129 + n], Bstg[(sl + 1) * 129 + n]);
        }
#pragma unroll
        for (int jj = 0; jj < 4; jj++) {
            const int j = tid + jj * 256;              // 1024
            const int p = j >> 4, sl = (j & 15) * 2;
            const uint32_t a = (uint32_t)(p * 64) + CSWZ(p, sl >> 3) + (sl & 7) * 2;
            *(uint32_t*)(sm + ST_A + a) =
                pack2h(xstg[sl * 65 + p] * ws_sh[s0 + sl],
                       xstg[(sl + 1) * 65 + p] * ws_sh[s0 + sl + 1]);
        }
        __syncthreads();
#pragma unroll
        for (int ki = 0; ki < 2; ki++) {
            const int chunk = ki * 2 + lhalf;
            uint32_t ah[2][4];
#pragma unroll
            for (int mi = 0; mi < 2; mi++) {
                const int r = warp_m * 32 + mi * 16 + lrow;
                const uint32_t off = (uint32_t)(r * 64) + CSWZ(r, chunk);
                ldm4(ah[mi], sb + ST_A + off);
            }
            uint32_t bh[2][4];
#pragma unroll
            for (int nj = 0; nj < 2; nj++) {
                const int r = warp_n * 32 + nj * 16 + lrow;
                const uint32_t off = (uint32_t)(r * 64) + CSWZ(r, chunk);
                ldm4(bh[nj], sb + ST_B + off);
            }
#pragma unroll
            for (int mi = 0; mi < 2; mi++)
#pragma unroll
                for (int nj = 0; nj < 4; nj++) {
                    const int g = nj >> 1, hh = nj & 1;
                    mma16816h(acc[mi][nj], ah[mi], bh[g][hh], bh[g][hh + 2]);
                }
        }
        __syncthreads();
    }

#pragma unroll
    for (int mi = 0; mi < 2; mi++)
#pragma unroll
        for (int nj = 0; nj < 4; nj++) {
            const int row = warp_m * 32 + mi * 16 + (lane >> 2);
            const int col = warp_n * 32 + nj * 8 + (lane & 3) * 2;
            float* dst = &g_states[(size_t)blk * HD * DS + (size_t)row * DS + col];
            *(float2*)dst = make_float2(acc[mi][nj][0], acc[mi][nj][1]);
            *(float2*)(dst + 8 * DS) = make_float2(acc[mi][nj][2], acc[mi][nj][3]);
        }
}

// ---------------- inter-chunk recurrence (sequential over chunks) --------
__global__ __launch_bounds__(256) void kernel_scan() {
    const int b = blockIdx.x >> 5;
    const int h = blockIdx.x & 31;
    const int tid = threadIdx.x;
    float4 prev[8];
#pragma unroll
    for (int i = 0; i < 8; i++) prev[i] = make_float4(0.f, 0.f, 0.f, 0.f);
    for (int c = 0; c < NC; c++) {
        int blk = (b * NC + c) * NH + h;
        float cd = __expf(g_cumA[blk * CH + CH - 1]);
        const float4* st = (const float4*)&g_states[(size_t)blk * HD * DS];
        float4* pv = (float4*)&g_prev[(size_t)blk * HD * DS];
#pragma unroll
        for (int i = 0; i < 8; i++) {
            float4 s = st[tid + i * 256];
            float4 pr = prev[i];
            pv[tid + i * 256] = pr;
            prev[i] = make_float4(pr.x * cd + s.x, pr.y * cd + s.y,
                                  pr.z * cd + s.z, pr.w * cd + s.w);
        }
    }
}

// ---------------- fused Yd + Yoff + D*x on fp16 HMMA ---------------------
// Both operands single fp16. 1 MMA per pair.
#define YO_CUMA  0
#define YO_DT    1024
#define YO_EA    2048
#define YO_W     3072                    // 16KB [256][64B]
#define YO_XT    19456                   // 4KB [64][64B]
#define YO_STAGE 23552                   // [32][65] fp32 = 8320 B
#define YO_SMEM  31872

__global__ __launch_bounds__(256) void kernel_ydoff_mma(const float* __restrict__ Dv) {
    extern __shared__ __align__(1024) char sm[];
    const int blk = blockIdx.x;
    const int h = blk & (NH - 1);
    const int bc = blk / NH;
    const int b = bc / NC, c = bc - b * NC;
    const int tid = threadIdx.x;
    const int base_l = b * L_ + c * CH;
    const uint32_t sb = smem_u32(sm);
    float* cumA_sh = (float*)(sm + YO_CUMA);
    float* dt_sh = (float*)(sm + YO_DT);
    float* eA_sh = (float*)(sm + YO_EA);
    float* stg = (float*)(sm + YO_STAGE);
    const float* Gb = g_G + (size_t)bc * CH * CH;

    cumA_sh[tid] = g_cumA[blk * CH + tid];
    dt_sh[tid] = g_dt[(base_l + tid) * NH + h];
    __syncthreads();
    eA_sh[tid] = __expf(cumA_sh[tid]);
    __syncthreads();

    const int warp = tid >> 5, lane = tid & 31;
    const int lrow = (lane & 7) + ((lane >> 3) & 1) * 8;
    const int lhalf = lane >> 4;
    const int rb0 = warp * 16;
    const int rb1 = 240 - warp * 16;

    float acc[2][8][4];
#pragma unroll
    for (int a = 0; a < 2; a++)
#pragma unroll
        for (int bq = 0; bq < 8; bq++)
#pragma unroll
            for (int cq = 0; cq < 4; cq++) acc[a][bq][cq] = 0.f;

    // ---- phase 1: Yd over s-chunks (triangular) ----
    for (int s0 = 0; s0 < CH; s0 += 32) {
#pragma unroll
        for (int ii = 0; ii < 8; ii++) {
            const int i = tid + ii * 256;
            const int s = i >> 6, p = i & 63;
            stg[s * 65 + p] = g_xBC[(size_t)(base_l + s0 + s) * CD + h * HD + p];
        }
        __syncthreads();
        const int nent = (CH - s0) * 16;
        for (int j = tid; j < nent; j += 256) {
            const int t = s0 + (j >> 4), sl = (j & 15) * 2;
            const int sg = s0 + sl;
            const float cat = cumA_sh[t];
            float w0 = (t >= sg) ? Gb[t * CH + sg] * __expf(cat - cumA_sh[sg]) * dt_sh[sg] : 0.f;
            float w1 = (t >= sg + 1) ? Gb[t * CH + sg + 1] * __expf(cat - cumA_sh[sg + 1]) * dt_sh[sg + 1] : 0.f;
            const uint32_t a = (uint32_t)(t * 64) + CSWZ(t, sl >> 3) + (sl & 7) * 2;
            *(uint32_t*)(sm + YO_W + a) = pack2h(w0, w1);
        }
#pragma unroll
        for (int jj = 0; jj < 4; jj++) {
            const int j = tid + jj * 256;              // 1024
            const int p = j >> 4, sl = (j & 15) * 2;
            const uint32_t a = (uint32_t)(p * 64) + CSWZ(p, sl >> 3) + (sl & 7) * 2;
            *(uint32_t*)(sm + YO_XT + a) = pack2h(stg[sl * 65 + p], stg[(sl + 1) * 65 + p]);
        }
        __syncthreads();
        const bool act0 = (rb0 + 16 > s0);
        const bool act1 = (rb1 + 16 > s0);
        if (act0 || act1) {
#pragma unroll
            for (int ki = 0; ki < 2; ki++) {
                const int chunk = ki * 2 + lhalf;
                uint32_t bh[4][4];
#pragma unroll
                for (int nj = 0; nj < 4; nj++) {
                    const int r = nj * 16 + lrow;
                    const uint32_t off = (uint32_t)(r * 64) + CSWZ(r, chunk);
                    ldm4(bh[nj], sb + YO_XT + off);
                }
#pragma unroll
                for (int mi = 0; mi < 2; mi++) {
                    if (mi == 0 ? !act0 : !act1) continue;
                    const int r = (mi ? rb1 : rb0) + lrow;
                    const uint32_t off = (uint32_t)(r * 64) + CSWZ(r, chunk);
                    uint32_t ah[4];
                    ldm4(ah, sb + YO_W + off);
#pragma unroll
                    for (int nj = 0; nj < 8; nj++) {
                        const int g = nj >> 1, hh = nj & 1;
                        mma16816h(acc[mi][nj], ah, bh[g][hh], bh[g][hh + 2]);
                    }
                }
            }
        }
        __syncthreads();
    }

    // ---- phase 2: Yoff over n-chunks (dense) ----
    const float* prev_base = &g_prev[(size_t)blk * HD * DS];
    for (int n0 = 0; n0 < DS; n0 += 32) {
#pragma unroll
        for (int jj = 0; jj < 16; jj++) {
            const int j = tid + jj * 256;              // 4096
            const int t = j >> 4, nl = (j & 15) * 2;
            const float ea = eA_sh[t];
            const float* cp = &g_xBC[(size_t)(base_l + t) * CD + DSSM + DS + n0 + nl];
            const uint32_t a = (uint32_t)(t * 64) + CSWZ(t, nl >> 3) + (nl & 7) * 2;
            *(uint32_t*)(sm + YO_W + a) = pack2h(cp[0] * ea, cp[1] * ea);
        }
#pragma unroll
        for (int jj = 0; jj < 4; jj++) {
            const int j = tid + jj * 256;              // 1024
            const int p = j >> 4, nl = (j & 15) * 2;
            const float* pp = &prev_base[(size_t)p * DS + n0 + nl];
            const uint32_t a = (uint32_t)(p * 64) + CSWZ(p, nl >> 3) + (nl & 7) * 2;
            *(uint32_t*)(sm + YO_XT + a) = pack2h(pp[0], pp[1]);
        }
        __syncthreads();
#pragma unroll
        for (int ki = 0; ki < 2; ki++) {
            const int chunk = ki * 2 + lhalf;
            uint32_t bh[4][4];
#pragma unroll
            for (int nj = 0; nj < 4; nj++) {
                const int r = nj * 16 + lrow;
                const uint32_t off = (uint32_t)(r * 64) + CSWZ(r, chunk);
                ldm4(bh[nj], sb + YO_XT + off);
            }
#pragma unroll
            for (int mi = 0; mi < 2; mi++) {
                const int r = (mi ? rb1 : rb0) + lrow;
                const uint32_t off = (uint32_t)(r * 64) + CSWZ(r, chunk);
                uint32_t ah[4];
                ldm4(ah, sb + YO_W + off);
#pragma unroll
                for (int nj = 0; nj < 8; nj++) {
                    const int g = nj >> 1, hh = nj & 1;
                    mma16816h(acc[mi][nj], ah, bh[g][hh], bh[g][hh + 2]);
                }
            }
        }
        __syncthreads();
    }

    // ---- epilogue: + D[h]*x, write Y ----
    const float Dh = Dv[h];
#pragma unroll
    for (int mi = 0; mi < 2; mi++)
#pragma unroll
        for (int nj = 0; nj < 8; nj++) {
            const int row = (mi ? rb1 : rb0) + (lane >> 2);
            const int col = nj * 8 + (lane & 3) * 2;
            const size_t l0 = (size_t)(base_l + row);
            float2 x0 = *(const float2*)&g_xBC[l0 * CD + h * HD + col];
            float2 x1 = *(const float2*)&g_xBC[(l0 + 8) * CD + h * HD + col];
            *(float2*)&g_Y[l0 * DSSM + h * HD + col] =
                make_float2(acc[mi][nj][0] + Dh * x0.x, acc[mi][nj][1] + Dh * x0.y);
            *(float2*)&g_Y[(l0 + 8) * DSSM + h * HD + col] =
                make_float2(acc[mi][nj][2] + Dh * x1.x, acc[mi][nj][3] + Dh * x1.y);
        }
}

// ---------------- gated RMSNorm -> single fp16 ----------------
__global__ __launch_bounds__(256) void kernel_norm(const float* __restrict__ nw) {
    const int row = blockIdx.x;
    const int tid = threadIdx.x;
    const float* y = &g_Y[(size_t)row * DSSM];
    const float* z = &g_zx[(size_t)row * NZX];  // z = first DSSM cols
    float v[8];
    float sum = 0.f;
#pragma unroll
    for (int i = 0; i < 8; i++) {
        int cc = tid + i * 256;
        float zz = z[cc];
        float vv = y[cc] * (zz / (1.f + __expf(-zz)));
        v[i] = vv;
        sum += vv * vv;
    }
    __shared__ float red[256];
    red[tid] = sum;
    __syncthreads();
    for (int off = 128; off; off >>= 1) {
        if (tid < off) red[tid] += red[tid + off];
        __syncthreads();
    }
    const float scale = rsqrtf(red[0] * (1.f / DSSM) + 1e-5f);
#pragma unroll
    for (int i = 0; i < 8; i++) {
        int cc = tid + i * 256;
        g_ynh[(size_t)row * DSSM + cc] = __float2half_rn(v[i] * scale * nw[cc]);
    }
}

// ---------------- stream / event handles (host objects only; created once,
// no device memory involved — launched work is identical on every call) ---
static cudaStream_t s_str1 = nullptr, s_str2 = nullptr;
static cudaEvent_t s_eS = nullptr, s_eConv = nullptr, s_eCum = nullptr,
                   s_eG = nullptr, s_eWout = nullptr;

// ---------------- launch ----------------
extern "C" void kernel_launch(void* const* d_in, const int* in_sizes, int n_in,
                              void* d_out, int out_size) {
    const float* u     = (const float*)d_in[0];
    const int*   cidx  = (const int*)d_in[1];
    const float* W_in  = (const float*)d_in[2];
    const float* cw    = (const float*)d_in[3];
    const float* cb    = (const float*)d_in[4];
    const float* dtb   = (const float*)d_in[5];
    const float* A_log = (const float*)d_in[6];
    const float* Dv    = (const float*)d_in[7];
    const float* nw    = (const float*)d_in[8];
    const float* W_out = (const float*)d_in[9];
    float* out = (float*)d_out;

    float* zx_p;
    __half *uh, *wih, *woh, *ynh;
    cudaGetSymbolAddress((void**)&zx_p, g_zx);
    cudaGetSymbolAddress((void**)&uh, g_uh);
    cudaGetSymbolAddress((void**)&wih, g_wih);
    cudaGetSymbolAddress((void**)&woh, g_woh);
    cudaGetSymbolAddress((void**)&ynh, g_ynh);

    cudaFuncSetAttribute(gemm_mma_f16, cudaFuncAttributeMaxDynamicSharedMemorySize, GM_SMEM);
    cudaFuncSetAttribute(kernel_states_mma, cudaFuncAttributeMaxDynamicSharedMemorySize, ST_SMEM);
    cudaFuncSetAttribute(kernel_ydoff_mma, cudaFuncAttributeMaxDynamicSharedMemorySize, YO_SMEM);

    if (s_str1 == nullptr) {
        cudaStreamCreateWithFlags(&s_str1, cudaStreamNonBlocking);
        cudaStreamCreateWithFlags(&s_str2, cudaStreamNonBlocking);
        cudaEventCreateWithFlags(&s_eS, cudaEventDisableTiming);
        cudaEventCreateWithFlags(&s_eConv, cudaEventDisableTiming);
        cudaEventCreateWithFlags(&s_eCum, cudaEventDisableTiming);
        cudaEventCreateWithFlags(&s_eG, cudaEventDisableTiming);
        cudaEventCreateWithFlags(&s_eWout, cudaEventDisableTiming);
    }

    // fork side streams off the main stream
    cudaEventRecord(s_eS, 0);
    cudaStreamWaitEvent(s_str1, s_eS, 0);
    cudaStreamWaitEvent(s_str2, s_eS, 0);

    // side stream 1: exact fp32 dt -> cumsum (independent of gemm1 path)
    kernel_dt<<<(B_ * L_) / 16, 256, 0, s_str1>>>(u, W_in, dtb);
    kernel_cumA<<<B_ * NC * NH, 256, 0, s_str1>>>(A_log);
    cudaEventRecord(s_eCum, s_str1);

    // side stream 2: W_out fp16 convert (only needed by gemm2)
    {
        int n4 = (DM * DSSM) / 4;
        cvt_fp16<<<(n4 + 255) / 256, 256, 0, s_str2>>>(W_out, woh, n4);
        cudaEventRecord(s_eWout, s_str2);
    }

    // main stream: converts -> gemm1 -> conv
    {
        int n4 = (B_ * L_ * DM) / 4;
        cvt_fp16<<<(n4 + 255) / 256, 256>>>(u, uh, n4);
        n4 = (DIP * DM) / 4;
        cvt_fp16<<<(n4 + 255) / 256, 256>>>(W_in, wih, n4);
    }
    gemm_mma_f16<<<dim3(NZX / 128, (B_ * L_) / 128), 256, GM_SMEM>>>(
        uh, wih, zx_p, B_ * L_, NZX, DM, NZX);
    kernel_conv<<<B_ * L_, 256>>>(cidx, cw, cb);
    cudaEventRecord(s_eConv, 0);

    // side stream 1: G (depends only on conv), overlapped with states/scan
    cudaStreamWaitEvent(s_str1, s_eConv, 0);
    kernel_G<<<dim3(CH / 16, CH / 16, B_ * NC), dim3(16, 16), 0, s_str1>>>();
    cudaEventRecord(s_eG, s_str1);

    // main stream: states (needs conv + cumA) -> scan
    cudaStreamWaitEvent(0, s_eCum, 0);
    kernel_states_mma<<<B_ * NC * NH, 256, ST_SMEM>>>();
    kernel_scan<<<B_ * NH, 256>>>();

    // main stream: ydoff needs G too
    cudaStreamWaitEvent(0, s_eG, 0);
    kernel_ydoff_mma<<<B_ * NC * NH, 256, YO_SMEM>>>(Dv);
    kernel_norm<<<B_ * L_, 256>>>(nw);

    // gemm2 needs woh
    cudaStreamWaitEvent(0, s_eWout, 0);
    gemm_mma_f16<<<dim3(DM / 128, (B_ * L_) / 128), 256, GM_SMEM>>>(
        ynh, woh, out, B_ * L_, DM, DSSM, DM);
}

// round 15
// speedup vs baseline: 1.1502x; 1.0378x over previous
#include <cuda_runtime.h>
#include <cuda_bf16.h>
#include <cuda_fp16.h>
#include <math.h>
#include <stdint.h>

#define B_   2
#define L_   2048
#define DM   1024
#define DIP  4384
#define DSSM 2048
#define CD   2304
#define NZX  (DSSM + CD)               /* 4352 = z | xBC, dt handled separately */
#define NH   32
#define HD   64
#define DS   128
#define CH   256
#define NC   8

// ---------------- scratch (device globals; no allocation) ----------------
__device__ float g_zx[B_ * L_ * NZX];          // in-proj output (z | xBC)
__device__ float g_xBC[B_ * L_ * CD];          // post-conv+silu (x | B | C)
__device__ float g_dt[B_ * L_ * NH];           // softplus dt (computed in fp32)
__device__ float g_G[B_ * NC * CH * CH];       // per-chunk C@B^T (head-independent)
__device__ float g_cumA[B_ * NC * NH * CH];    // inclusive cumsum of dt*A per chunk
__device__ float g_states[B_ * NC * NH * HD * DS];
__device__ float g_prev[B_ * NC * NH * HD * DS];
__device__ float g_Y[B_ * L_ * DSSM];

// fp16 operand buffers for the two projection GEMMs
__device__ __half g_uh[B_ * L_ * DM];
__device__ __half g_wih[DIP * DM];             // W_in single fp16
__device__ __half g_woh[DM * DSSM];            // W_out single fp16
__device__ __half g_ynh[B_ * L_ * DSSM];

// ---------------- warp-level MMA helpers (arch-neutral PTX) ----------------
__device__ __forceinline__ uint32_t smem_u32(const void* p) {
    uint32_t a;
    asm("{ .reg .u64 t; cvta.to.shared.u64 t, %1; cvt.u32.u64 %0, t; }" : "=r"(a) : "l"(p));
    return a;
}
__device__ __forceinline__ void ldm4(uint32_t* r, uint32_t addr) {
    asm volatile("ldmatrix.sync.aligned.m8n8.x4.shared.b16 {%0,%1,%2,%3}, [%4];"
                 : "=r"(r[0]), "=r"(r[1]), "=r"(r[2]), "=r"(r[3]) : "r"(addr));
}
__device__ __forceinline__ void mma16816h(float* d, const uint32_t* a,
                                          uint32_t b0, uint32_t b1) {
    asm volatile(
        "mma.sync.aligned.m16n8k16.row.col.f32.f16.f16.f32 "
        "{%0,%1,%2,%3}, {%4,%5,%6,%7}, {%8,%9}, {%0,%1,%2,%3};"
        : "+f"(d[0]), "+f"(d[1]), "+f"(d[2]), "+f"(d[3])
        : "r"(a[0]), "r"(a[1]), "r"(a[2]), "r"(a[3]), "r"(b0), "r"(b1));
}
__device__ __forceinline__ void cpasync16(uint32_t dst, const void* src, int sz) {
    asm volatile("cp.async.cg.shared.global [%0], [%1], 16, %2;"
                 :: "r"(dst), "l"(src), "r"(sz) : "memory");
}
#define CP_COMMIT() asm volatile("cp.async.commit_group;" ::: "memory")
#define CP_WAIT0()  asm volatile("cp.async.wait_group 0;" ::: "memory")
#define CP_WAIT1()  asm volatile("cp.async.wait_group 1;" ::: "memory")

// chunk swizzle for 64-byte rows: conflict-free 8-row ldmatrix gathers
#define CSWZ(r, c) ((((c) ^ (((r) >> 1) & 3))) << 4)
// unit swizzle for 128-byte rows (standard SW128): unit' = unit ^ (r & 7)
#define SWZ8(r, c) ((((c) ^ ((r) & 7))) << 4)

__device__ __forceinline__ uint32_t pack2h(float a, float b) {
    __half2 H{__float2half_rn(a), __float2half_rn(b)};
    return *(uint32_t*)&H;
}

// ---------------- fp32 -> fp16 single convert ----------------
__global__ __launch_bounds__(256) void cvt_fp16(const float* __restrict__ src,
                                                __half* __restrict__ dst, int n4) {
    int i = blockIdx.x * 256 + threadIdx.x;
    if (i >= n4) return;
    float4 v = ((const float4*)src)[i];
    ((uint32_t*)dst)[2 * i + 0] = pack2h(v.x, v.y);
    ((uint32_t*)dst)[2 * i + 1] = pack2h(v.z, v.w);
}

// ---------------- single fp16 HMMA GEMM: C = A @ B^T ----------------------
// k-tile = 64 (128-byte rows, SW128 swizzle). Stage: A 16K | B 16K = 32KB;
// 3 stages = 96KB, 2 CTAs/SM.
#define GM_SMEM (3 * 32768)

__global__ __launch_bounds__(256, 2) void gemm_mma_f16(const __half* __restrict__ Ah,
                                                       const __half* __restrict__ Bh,
                                                       float* __restrict__ C,
                                                       int M, int N, int K, int ldc) {
    extern __shared__ __align__(1024) char sm[];
    const int tid = threadIdx.x;
    const int m0 = blockIdx.y * 128, n0 = blockIdx.x * 128;
    const uint32_t sb0 = smem_u32(sm);
    const int warp = tid >> 5, lane = tid & 31;
    const int warp_m = warp & 3, warp_n = warp >> 2;
    const int KT = K >> 6;

    float acc[2][8][4];
#pragma unroll
    for (int a = 0; a < 2; a++)
#pragma unroll
        for (int b = 0; b < 8; b++)
#pragma unroll
            for (int c = 0; c < 4; c++) acc[a][b][c] = 0.f;

    auto load_stage = [&](int kt, int s) {
        const uint32_t sb = sb0 + s * 32768;
        const int k0 = kt << 6;
#pragma unroll
        for (int ii = 0; ii < 4; ii++) {
            const int i = tid + ii * 256;              // 1024 float4 per operand
            const int r = i >> 3, c = i & 7;
            const uint32_t sw = (uint32_t)(r * 128) + SWZ8(r, c);
            const size_t ga = (size_t)(m0 + r) * K + k0 + c * 8;
            cpasync16(sb + sw, Ah + ga, 16);
            const int rb = (n0 + r < N) ? (n0 + r) : (N - 1);
            const int bs = (n0 + r < N) ? 16 : 0;
            const size_t gb = (size_t)rb * K + k0 + c * 8;
            cpasync16(sb + 16384 + sw, Bh + gb, bs);
        }
    };

    load_stage(0, 0);
    CP_COMMIT();
    if (KT > 1) {
        load_stage(1, 1);
        CP_COMMIT();
    }

    const int lrow = (lane & 7) + ((lane >> 3) & 1) * 8;
    const int lhalf = lane >> 4;

    for (int kt = 0; kt < KT; kt++) {
        if (kt + 1 < KT) CP_WAIT1(); else CP_WAIT0();
        __syncthreads();
        if (kt + 2 < KT) {
            load_stage(kt + 2, (kt + 2) % 3);
            CP_COMMIT();
        }

        const uint32_t sb = sb0 + (kt % 3) * 32768;
#pragma unroll
        for (int ki = 0; ki < 4; ki++) {
            const int unit = ki * 2 + lhalf;           // 16-byte unit within 128-B row
            uint32_t ah[2][4];
#pragma unroll
            for (int mi = 0; mi < 2; mi++) {
                const int r = warp_m * 32 + mi * 16 + lrow;
                const uint32_t off = (uint32_t)(r * 128) + SWZ8(r, unit);
                ldm4(ah[mi], sb + off);
            }
            uint32_t bh[4][4];
#pragma unroll
            for (int nj = 0; nj < 4; nj++) {
                const int r = warp_n * 64 + nj * 16 + lrow;
                const uint32_t off = (uint32_t)(r * 128) + SWZ8(r, unit);
                ldm4(bh[nj], sb + 16384 + off);
            }
#pragma unroll
            for (int mi = 0; mi < 2; mi++)
#pragma unroll
                for (int nj = 0; nj < 8; nj++) {
                    const int g = nj >> 1, h = nj & 1;
                    mma16816h(acc[mi][nj], ah[mi], bh[g][h], bh[g][h + 2]);
                }
        }
    }

#pragma unroll
    for (int mi = 0; mi < 2; mi++)
#pragma unroll
        for (int nj = 0; nj < 8; nj++) {
            const int row = m0 + warp_m * 32 + mi * 16 + (lane >> 2);
            const int col = n0 + warp_n * 64 + nj * 8 + (lane & 3) * 2;
            if (col < N) {
                float2 v0 = make_float2(acc[mi][nj][0], acc[mi][nj][1]);
                float2 v1 = make_float2(acc[mi][nj][2], acc[mi][nj][3]);
                *(float2*)&C[(size_t)row * ldc + col] = v0;
                *(float2*)&C[(size_t)(row + 8) * ldc + col] = v1;
            }
        }
}

// ---------------- exact fp32 dt: softplus(u @ W_dt^T + bias) -------------
// 256 CTAs x 16 rows (proven R11 configuration).
__global__ __launch_bounds__(256) void kernel_dt(const float* __restrict__ u,
                                                 const float* __restrict__ W_in,
                                                 const float* __restrict__ dtb) {
    __shared__ float ush[16 * 68];
    __shared__ float wsh[32 * 68];
    const int tid = threadIdx.x;
    const int row0 = blockIdx.x * 16;
    const int col = tid & 31, r0 = (tid >> 5) * 2;
    float acc[2] = {0.f, 0.f};

    for (int k0 = 0; k0 < DM; k0 += 64) {
        {
            const int i = tid;                       // 256 = 16*16
            const int r = i >> 4, c = (i & 15) * 4;
            *(float4*)&ush[r * 68 + c] = *(const float4*)&u[(size_t)(row0 + r) * DM + k0 + c];
        }
#pragma unroll
        for (int ii = 0; ii < 2; ii++) {
            const int i = tid + ii * 256;
            const int r = i >> 4, c = (i & 15) * 4;
            *(float4*)&wsh[r * 68 + c] =
                *(const float4*)&W_in[(size_t)(NZX + r) * DM + k0 + c];
        }
        __syncthreads();
#pragma unroll 8
        for (int k = 0; k < 64; k++) {
            const float w = wsh[col * 68 + k];
            acc[0] += ush[(r0 + 0) * 68 + k] * w;
            acc[1] += ush[(r0 + 1) * 68 + k] * w;
        }
        __syncthreads();
    }
    const float bias = dtb[col];
#pragma unroll
    for (int j = 0; j < 2; j++) {
        float x = acc[j] + bias;
        g_dt[(row0 + r0 + j) * NH + col] = (x > 20.f) ? x : log1pf(expf(x));
    }
}

// ---------------- tree conv + silu ----------------
__global__ __launch_bounds__(256) void kernel_conv(const int* __restrict__ cidx,
                                                   const float* __restrict__ cw,
                                                   const float* __restrict__ cb) {
    const int bt = blockIdx.x;           // b*L_ + t
    const int b = bt / L_, t = bt - b * L_;
    const int tid = threadIdx.x;

    __shared__ int idx[4];
    if (tid < 4) idx[tid] = cidx[(size_t)b * 4 * L_ + 4 * t + tid];
    __syncthreads();
    const int i0 = idx[0], i1 = idx[1], i2 = idx[2], i3 = idx[3];

    for (int c = tid; c < CD; c += 256) {
        float acc = cb[c];
        const float* w = cw + c * 4;
        if (i0) acc += g_zx[(size_t)(b * L_ + i0 - 1) * NZX + DSSM + c] * w[0];
        if (i1) acc += g_zx[(size_t)(b * L_ + i1 - 1) * NZX + DSSM + c] * w[1];
        if (i2) acc += g_zx[(size_t)(b * L_ + i2 - 1) * NZX + DSSM + c] * w[2];
        if (i3) acc += g_zx[(size_t)(b * L_ + i3 - 1) * NZX + DSSM + c] * w[3];
        g_xBC[(size_t)bt * CD + c] = acc / (1.f + __expf(-acc));   // silu
    }
}

// ---------------- per-(b,c,h) inclusive cumsum of dt*A ----------------
__global__ __launch_bounds__(256) void kernel_cumA(const float* __restrict__ A_log) {
    const int blk = blockIdx.x;                 // (b*NC+c)*NH + h
    const int h = blk & (NH - 1);
    const int bc = blk / NH;
    const int b = bc / NC, c = bc - b * NC;
    const int t = threadIdx.x;
    const float Ah = -expf(A_log[h]);
    const int l = b * L_ + c * CH + t;
    __shared__ float s[CH];
    s[t] = g_dt[l * NH + h] * Ah;
    __syncthreads();
    for (int off = 1; off < CH; off <<= 1) {
        float add = (t >= off) ? s[t - off] : 0.f;
        __syncthreads();
        s[t] += add;
        __syncthreads();
    }
    g_cumA[blk * CH + t] = s[t];
}

// ---------------- G = C @ B^T per (b,chunk): lower-triangle blocks only --
__global__ void kernel_G() {
    const int bc = blockIdx.z;                 // b*NC + c
    const int t0 = blockIdx.y * 16, s0 = blockIdx.x * 16;
    if (t0 + 16 <= s0) return;                 // upper triangle never read
    const int tx = threadIdx.x, ty = threadIdx.y;
    const int tid = ty * 16 + tx;
    __shared__ float Cs[16][129];
    __shared__ float Bs[16][129];
    const int b = bc / NC, c = bc - b * NC;
    const int base_l = b * L_ + c * CH;
    for (int i = tid; i < 16 * 128; i += 256) {
        int row = i >> 7, n = i & 127;
        Cs[row][n] = g_xBC[(size_t)(base_l + t0 + row) * CD + DSSM + DS + n];
        Bs[row][n] = g_xBC[(size_t)(base_l + s0 + row) * CD + DSSM + n];
    }
    __syncthreads();
    float acc = 0.f;
#pragma unroll 8
    for (int n = 0; n < 128; n++) acc += Cs[ty][n] * Bs[tx][n];
    g_G[((size_t)bc * CH + t0 + ty) * CH + s0 + tx] = acc;
}

// ---------------- states on fp16 HMMA: S[p,n] = sum_s ws[s]*x[s,p]*B[s,n]
// Both operands single fp16. 1 MMA per pair.
#define ST_CUMA 0
#define ST_WS   1024
#define ST_A    2048                     // 4KB
#define ST_B    6144                     // 8KB
#define ST_BSTG 14336                    // [32][129] fp32 = 16512 B
#define ST_XSTG 30848                    // [32][65]  fp32 = 8320 B
#define ST_SMEM 39168

__global__ __launch_bounds__(256) void kernel_states_mma() {
    extern __shared__ __align__(1024) char sm[];
    const int blk = blockIdx.x;
    const int h = blk & (NH - 1);
    const int bc = blk / NH;
    const int b = bc / NC, c = bc - b * NC;
    const int tid = threadIdx.x;
    const int base_l = b * L_ + c * CH;
    const uint32_t sb = smem_u32(sm);
    float* cumA_sh = (float*)(sm + ST_CUMA);
    float* ws_sh = (float*)(sm + ST_WS);
    float* Bstg = (float*)(sm + ST_BSTG);
    float* xstg = (float*)(sm + ST_XSTG);

    cumA_sh[tid] = g_cumA[blk * CH + tid];
    __syncthreads();
    ws_sh[tid] = g_dt[(base_l + tid) * NH + h] * __expf(cumA_sh[CH - 1] - cumA_sh[tid]);
    __syncthreads();

    const int warp = tid >> 5, lane = tid & 31;
    const int warp_m = warp & 1, warp_n = warp >> 1;
    const int lrow = (lane & 7) + ((lane >> 3) & 1) * 8;
    const int lhalf = lane >> 4;

    float acc[2][4][4];
#pragma unroll
    for (int a = 0; a < 2; a++)
#pragma unroll
        for (int bq = 0; bq < 4; bq++)
#pragma unroll
            for (int cq = 0; cq < 4; cq++) acc[a][bq][cq] = 0.f;

    for (int s0 = 0; s0 < CH; s0 += 32) {
#pragma unroll
        for (int ii = 0; ii < 16; ii++) {
            const int i = tid + ii * 256;
            const int s = i >> 7, n = i & 127;
            Bstg[s * 129 + n] = g_xBC[(size_t)(base_l + s0 + s) * CD + DSSM + n];
        }
#pragma unroll
        for (int ii = 0; ii < 8; ii++) {
            const int i = tid + ii * 256;
            const int s = i >> 6, p = i & 63;
            xstg[s * 65 + p] = g_xBC[(size_t)(base_l + s0 + s) * CD + h * HD + p];
        }
        __syncthreads();
#pragma unroll
        for (int jj = 0; jj < 8; jj++) {
            const int j = tid + jj * 256;              // 2048
            const int n = j >> 4, sl = (j & 15) * 2;
            const uint32_t a = (uint32_t)(n * 64) + CSWZ(n, sl >> 3) + (sl & 7) * 2;
            *(uint32_t*)(sm + ST_B + a) = pack2h(Bstg[sl * 129 + n], Bstg[(sl + 1) * 129 + n]);
        }
#pragma unroll
        for (int jj = 0; jj < 4; jj++) {
            const int j = tid + jj * 256;              // 1024
            const int p = j >> 4, sl = (j & 15) * 2;
            const uint32_t a = (uint32_t)(p * 64) + CSWZ(p, sl >> 3) + (sl & 7) * 2;
            *(uint32_t*)(sm + ST_A + a) =
                pack2h(xstg[sl * 65 + p] * ws_sh[s0 + sl],
                       xstg[(sl + 1) * 65 + p] * ws_sh[s0 + sl + 1]);
        }
        __syncthreads();
#pragma unroll
        for (int ki = 0; ki < 2; ki++) {
            const int chunk = ki * 2 + lhalf;
            uint32_t ah[2][4];
#pragma unroll
            for (int mi = 0; mi < 2; mi++) {
                const int r = warp_m * 32 + mi * 16 + lrow;
                const uint32_t off = (uint32_t)(r * 64) + CSWZ(r, chunk);
                ldm4(ah[mi], sb + ST_A + off);
            }
            uint32_t bh[2][4];
#pragma unroll
            for (int nj = 0; nj < 2; nj++) {
                const int r = warp_n * 32 + nj * 16 + lrow;
                const uint32_t off = (uint32_t)(r * 64) + CSWZ(r, chunk);
                ldm4(bh[nj], sb + ST_B + off);
            }
#pragma unroll
            for (int mi = 0; mi < 2; mi++)
#pragma unroll
                for (int nj = 0; nj < 4; nj++) {
                    const int g = nj >> 1, hh = nj & 1;
                    mma16816h(acc[mi][nj], ah[mi], bh[g][hh], bh[g][hh + 2]);
                }
        }
        __syncthreads();
    }

#pragma unroll
    for (int mi = 0; mi < 2; mi++)
#pragma unroll
        for (int nj = 0; nj < 4; nj++) {
            const int row = warp_m * 32 + mi * 16 + (lane >> 2);
            const int col = warp_n * 32 + nj * 8 + (lane & 3) * 2;
            float* dst = &g_states[(size_t)blk * HD * DS + (size_t)row * DS + col];
            *(float2*)dst = make_float2(acc[mi][nj][0], acc[mi][nj][1]);
            *(float2*)(dst + 8 * DS) = make_float2(acc[mi][nj][2], acc[mi][nj][3]);
        }
}

// ---------------- inter-chunk recurrence (sequential over chunks) --------
__global__ __launch_bounds__(256) void kernel_scan() {
    const int b = blockIdx.x >> 5;
    const int h = blockIdx.x & 31;
    const int tid = threadIdx.x;
    float4 prev[8];
#pragma unroll
    for (int i = 0; i < 8; i++) prev[i] = make_float4(0.f, 0.f, 0.f, 0.f);
    for (int c = 0; c < NC; c++) {
        int blk = (b * NC + c) * NH + h;
        float cd = __expf(g_cumA[blk * CH + CH - 1]);
        const float4* st = (const float4*)&g_states[(size_t)blk * HD * DS];
        float4* pv = (float4*)&g_prev[(size_t)blk * HD * DS];
#pragma unroll
        for (int i = 0; i < 8; i++) {
            float4 s = st[tid + i * 256];
            float4 pr = prev[i];
            pv[tid + i * 256] = pr;
            prev[i] = make_float4(pr.x * cd + s.x, pr.y * cd + s.y,
                                  pr.z * cd + s.z, pr.w * cd + s.w);
        }
    }
}

// ---------------- fused Yd + Yoff + D*x on fp16 HMMA ---------------------
// Both operands single fp16. 1 MMA per pair.
#define YO_CUMA  0
#define YO_DT    1024
#define YO_EA    2048
#define YO_W     3072                    // 16KB [256][64B]
#define YO_XT    19456                   // 4KB [64][64B]
#define YO_STAGE 23552                   // [32][65] fp32 = 8320 B
#define YO_SMEM  31872

__global__ __launch_bounds__(256) void kernel_ydoff_mma(const float* __restrict__ Dv) {
    extern __shared__ __align__(1024) char sm[];
    const int blk = blockIdx.x;
    const int h = blk & (NH - 1);
    const int bc = blk / NH;
    const int b = bc / NC, c = bc - b * NC;
    const int tid = threadIdx.x;
    const int base_l = b * L_ + c * CH;
    const uint32_t sb = smem_u32(sm);
    float* cumA_sh = (float*)(sm + YO_CUMA);
    float* dt_sh = (float*)(sm + YO_DT);
    float* eA_sh = (float*)(sm + YO_EA);
    float* stg = (float*)(sm + YO_STAGE);
    const float* Gb = g_G + (size_t)bc * CH * CH;

    cumA_sh[tid] = g_cumA[blk * CH + tid];
    dt_sh[tid] = g_dt[(base_l + tid) * NH + h];
    __syncthreads();
    eA_sh[tid] = __expf(cumA_sh[tid]);
    __syncthreads();

    const int warp = tid >> 5, lane = tid & 31;
    const int lrow = (lane & 7) + ((lane >> 3) & 1) * 8;
    const int lhalf = lane >> 4;
    const int rb0 = warp * 16;
    const int rb1 = 240 - warp * 16;

    float acc[2][8][4];
#pragma unroll
    for (int a = 0; a < 2; a++)
#pragma unroll
        for (int bq = 0; bq < 8; bq++)
#pragma unroll
            for (int cq = 0; cq < 4; cq++) acc[a][bq][cq] = 0.f;

    // ---- phase 1: Yd over s-chunks (triangular) ----
    for (int s0 = 0; s0 < CH; s0 += 32) {
#pragma unroll
        for (int ii = 0; ii < 8; ii++) {
            const int i = tid + ii * 256;
            const int s = i >> 6, p = i & 63;
            stg[s * 65 + p] = g_xBC[(size_t)(base_l + s0 + s) * CD + h * HD + p];
        }
        __syncthreads();
        const int nent = (CH - s0) * 16;
        for (int j = tid; j < nent; j += 256) {
            const int t = s0 + (j >> 4), sl = (j & 15) * 2;
            const int sg = s0 + sl;
            const float cat = cumA_sh[t];
            float w0 = (t >= sg) ? Gb[t * CH + sg] * __expf(cat - cumA_sh[sg]) * dt_sh[sg] : 0.f;
            float w1 = (t >= sg + 1) ? Gb[t * CH + sg + 1] * __expf(cat - cumA_sh[sg + 1]) * dt_sh[sg + 1] : 0.f;
            const uint32_t a = (uint32_t)(t * 64) + CSWZ(t, sl >> 3) + (sl & 7) * 2;
            *(uint32_t*)(sm + YO_W + a) = pack2h(w0, w1);
        }
#pragma unroll
        for (int jj = 0; jj < 4; jj++) {
            const int j = tid + jj * 256;              // 1024
            const int p = j >> 4, sl = (j & 15) * 2;
            const uint32_t a = (uint32_t)(p * 64) + CSWZ(p, sl >> 3) + (sl & 7) * 2;
            *(uint32_t*)(sm + YO_XT + a) = pack2h(stg[sl * 65 + p], stg[(sl + 1) * 65 + p]);
        }
        __syncthreads();
        const bool act0 = (rb0 + 16 > s0);
        const bool act1 = (rb1 + 16 > s0);
        if (act0 || act1) {
#pragma unroll
            for (int ki = 0; ki < 2; ki++) {
                const int chunk = ki * 2 + lhalf;
                uint32_t bh[4][4];
#pragma unroll
                for (int nj = 0; nj < 4; nj++) {
                    const int r = nj * 16 + lrow;
                    const uint32_t off = (uint32_t)(r * 64) + CSWZ(r, chunk);
                    ldm4(bh[nj], sb + YO_XT + off);
                }
#pragma unroll
                for (int mi = 0; mi < 2; mi++) {
                    if (mi == 0 ? !act0 : !act1) continue;
                    const int r = (mi ? rb1 : rb0) + lrow;
                    const uint32_t off = (uint32_t)(r * 64) + CSWZ(r, chunk);
                    uint32_t ah[4];
                    ldm4(ah, sb + YO_W + off);
#pragma unroll
                    for (int nj = 0; nj < 8; nj++) {
                        const int g = nj >> 1, hh = nj & 1;
                        mma16816h(acc[mi][nj], ah, bh[g][hh], bh[g][hh + 2]);
                    }
                }
            }
        }
        __syncthreads();
    }

    // ---- phase 2: Yoff over n-chunks (dense) ----
    const float* prev_base = &g_prev[(size_t)blk * HD * DS];
    for (int n0 = 0; n0 < DS; n0 += 32) {
#pragma unroll
        for (int jj = 0; jj < 16; jj++) {
            const int j = tid + jj * 256;              // 4096
            const int t = j >> 4, nl = (j & 15) * 2;
            const float ea = eA_sh[t];
            const float* cp = &g_xBC[(size_t)(base_l + t) * CD + DSSM + DS + n0 + nl];
            const uint32_t a = (uint32_t)(t * 64) + CSWZ(t, nl >> 3) + (nl & 7) * 2;
            *(uint32_t*)(sm + YO_W + a) = pack2h(cp[0] * ea, cp[1] * ea);
        }
#pragma unroll
        for (int jj = 0; jj < 4; jj++) {
            const int j = tid + jj * 256;              // 1024
            const int p = j >> 4, nl = (j & 15) * 2;
            const float* pp = &prev_base[(size_t)p * DS + n0 + nl];
            const uint32_t a = (uint32_t)(p * 64) + CSWZ(p, nl >> 3) + (nl & 7) * 2;
            *(uint32_t*)(sm + YO_XT + a) = pack2h(pp[0], pp[1]);
        }
        __syncthreads();
#pragma unroll
        for (int ki = 0; ki < 2; ki++) {
            const int chunk = ki * 2 + lhalf;
            uint32_t bh[4][4];
#pragma unroll
            for (int nj = 0; nj < 4; nj++) {
                const int r = nj * 16 + lrow;
                const uint32_t off = (uint32_t)(r * 64) + CSWZ(r, chunk);
                ldm4(bh[nj], sb + YO_XT + off);
            }
#pragma unroll
            for (int mi = 0; mi < 2; mi++) {
                const int r = (mi ? rb1 : rb0) + lrow;
                const uint32_t off = (uint32_t)(r * 64) + CSWZ(r, chunk);
                uint32_t ah[4];
                ldm4(ah, sb + YO_W + off);
#pragma unroll
                for (int nj = 0; nj < 8; nj++) {
                    const int g = nj >> 1, hh = nj & 1;
                    mma16816h(acc[mi][nj], ah, bh[g][hh], bh[g][hh + 2]);
                }
            }
        }
        __syncthreads();
    }

    // ---- epilogue: + D[h]*x, write Y ----
    const float Dh = Dv[h];
#pragma unroll
    for (int mi = 0; mi < 2; mi++)
#pragma unroll
        for (int nj = 0; nj < 8; nj++) {
            const int row = (mi ? rb1 : rb0) + (lane >> 2);
            const int col = nj * 8 + (lane & 3) * 2;
            const size_t l0 = (size_t)(base_l + row);
            float2 x0 = *(const float2*)&g_xBC[l0 * CD + h * HD + col];
            float2 x1 = *(const float2*)&g_xBC[(l0 + 8) * CD + h * HD + col];
            *(float2*)&g_Y[l0 * DSSM + h * HD + col] =
                make_float2(acc[mi][nj][0] + Dh * x0.x, acc[mi][nj][1] + Dh * x0.y);
            *(float2*)&g_Y[(l0 + 8) * DSSM + h * HD + col] =
                make_float2(acc[mi][nj][2] + Dh * x1.x, acc[mi][nj][3] + Dh * x1.y);
        }
}

// ---------------- gated RMSNorm -> single fp16 ----------------
__global__ __launch_bounds__(256) void kernel_norm(const float* __restrict__ nw) {
    const int row = blockIdx.x;
    const int tid = threadIdx.x;
    const float* y = &g_Y[(size_t)row * DSSM];
    const float* z = &g_zx[(size_t)row * NZX];  // z = first DSSM cols
    float v[8];
    float sum = 0.f;
#pragma unroll
    for (int i = 0; i < 8; i++) {
        int cc = tid + i * 256;
        float zz = z[cc];
        float vv = y[cc] * (zz / (1.f + __expf(-zz)));
        v[i] = vv;
        sum += vv * vv;
    }
    __shared__ float red[256];
    red[tid] = sum;
    __syncthreads();
    for (int off = 128; off; off >>= 1) {
        if (tid < off) red[tid] += red[tid + off];
        __syncthreads();
    }
    const float scale = rsqrtf(red[0] * (1.f / DSSM) + 1e-5f);
#pragma unroll
    for (int i = 0; i < 8; i++) {
        int cc = tid + i * 256;
        g_ynh[(size_t)row * DSSM + cc] = __float2half_rn(v[i] * scale * nw[cc]);
    }
}

// ---------------- stream / event handles (host objects only; created once,
// no device memory involved — launched work is identical on every call) ---
static cudaStream_t s_str1 = nullptr, s_str2 = nullptr;
static cudaEvent_t s_eS = nullptr, s_eConv = nullptr, s_eCum = nullptr,
                   s_eG = nullptr, s_eWout = nullptr, s_eCvt = nullptr,
                   s_eZ = nullptr;

// ---------------- launch ----------------
extern "C" void kernel_launch(void* const* d_in, const int* in_sizes, int n_in,
                              void* d_out, int out_size) {
    const float* u     = (const float*)d_in[0];
    const int*   cidx  = (const int*)d_in[1];
    const float* W_in  = (const float*)d_in[2];
    const float* cw    = (const float*)d_in[3];
    const float* cb    = (const float*)d_in[4];
    const float* dtb   = (const float*)d_in[5];
    const float* A_log = (const float*)d_in[6];
    const float* Dv    = (const float*)d_in[7];
    const float* nw    = (const float*)d_in[8];
    const float* W_out = (const float*)d_in[9];
    float* out = (float*)d_out;

    float* zx_p;
    __half *uh, *wih, *woh, *ynh;
    cudaGetSymbolAddress((void**)&zx_p, g_zx);
    cudaGetSymbolAddress((void**)&uh, g_uh);
    cudaGetSymbolAddress((void**)&wih, g_wih);
    cudaGetSymbolAddress((void**)&woh, g_woh);
    cudaGetSymbolAddress((void**)&ynh, g_ynh);

    cudaFuncSetAttribute(gemm_mma_f16, cudaFuncAttributeMaxDynamicSharedMemorySize, GM_SMEM);
    cudaFuncSetAttribute(kernel_states_mma, cudaFuncAttributeMaxDynamicSharedMemorySize, ST_SMEM);
    cudaFuncSetAttribute(kernel_ydoff_mma, cudaFuncAttributeMaxDynamicSharedMemorySize, YO_SMEM);

    if (s_str1 == nullptr) {
        cudaStreamCreateWithFlags(&s_str1, cudaStreamNonBlocking);
        cudaStreamCreateWithFlags(&s_str2, cudaStreamNonBlocking);
        cudaEventCreateWithFlags(&s_eS, cudaEventDisableTiming);
        cudaEventCreateWithFlags(&s_eConv, cudaEventDisableTiming);
        cudaEventCreateWithFlags(&s_eCum, cudaEventDisableTiming);
        cudaEventCreateWithFlags(&s_eG, cudaEventDisableTiming);
        cudaEventCreateWithFlags(&s_eWout, cudaEventDisableTiming);
        cudaEventCreateWithFlags(&s_eCvt, cudaEventDisableTiming);
        cudaEventCreateWithFlags(&s_eZ, cudaEventDisableTiming);
    }

    // fork side streams off the main stream
    cudaEventRecord(s_eS, 0);
    cudaStreamWaitEvent(s_str1, s_eS, 0);
    cudaStreamWaitEvent(s_str2, s_eS, 0);

    // side stream 1: exact fp32 dt -> cumsum (independent of gemm1 path)
    kernel_dt<<<(B_ * L_) / 16, 256, 0, s_str1>>>(u, W_in, dtb);
    kernel_cumA<<<B_ * NC * NH, 256, 0, s_str1>>>(A_log);
    cudaEventRecord(s_eCum, s_str1);

    // side stream 2: W_out fp16 convert (only needed by gemm2)
    {
        int n4 = (DM * DSSM) / 4;
        cvt_fp16<<<(n4 + 255) / 256, 256, 0, s_str2>>>(W_out, woh, n4);
    }

    // main stream: converts
    {
        int n4 = (B_ * L_ * DM) / 4;
        cvt_fp16<<<(n4 + 255) / 256, 256>>>(u, uh, n4);
        n4 = (DIP * DM) / 4;
        cvt_fp16<<<(n4 + 255) / 256, 256>>>(W_in, wih, n4);
    }
    cudaEventRecord(s_eCvt, 0);

    // side stream 2: gemm1 z-slice (cols 0..2047, not needed until norm)
    cudaStreamWaitEvent(s_str2, s_eCvt, 0);
    gemm_mma_f16<<<dim3(DSSM / 128, (B_ * L_) / 128), 256, GM_SMEM, s_str2>>>(
        uh, wih, zx_p, B_ * L_, DSSM, DM, NZX);
    cudaEventRecord(s_eZ, s_str2);
    {
        int n4 = 0; (void)n4;
    }
    cudaEventRecord(s_eWout, s_str2);

    // main stream: gemm1 xBC-slice (cols 2048..4351) -> conv
    gemm_mma_f16<<<dim3(CD / 128, (B_ * L_) / 128), 256, GM_SMEM>>>(
        uh, wih + (size_t)DSSM * DM, zx_p + DSSM, B_ * L_, CD, DM, NZX);
    kernel_conv<<<B_ * L_, 256>>>(cidx, cw, cb);
    cudaEventRecord(s_eConv, 0);

    // side stream 1: G (depends only on conv), overlapped with states/scan
    cudaStreamWaitEvent(s_str1, s_eConv, 0);
    kernel_G<<<dim3(CH / 16, CH / 16, B_ * NC), dim3(16, 16), 0, s_str1>>>();
    cudaEventRecord(s_eG, s_str1);

    // main stream: states (needs conv + cumA) -> scan
    cudaStreamWaitEvent(0, s_eCum, 0);
    kernel_states_mma<<<B_ * NC * NH, 256, ST_SMEM>>>();
    kernel_scan<<<B_ * NH, 256>>>();

    // main stream: ydoff needs G too
    cudaStreamWaitEvent(0, s_eG, 0);
    kernel_ydoff_mma<<<B_ * NC * NH, 256, YO_SMEM>>>(Dv);

    // norm needs the z slice of gemm1
    cudaStreamWaitEvent(0, s_eZ, 0);
    kernel_norm<<<B_ * L_, 256>>>(nw);

    // gemm2 needs woh
    cudaStreamWaitEvent(0, s_eWout, 0);
    gemm_mma_f16<<<dim3(DM / 128, (B_ * L_) / 128), 256, GM_SMEM>>>(
        ynh, woh, out, B_ * L_, DM, DSSM, DM);
}